// round 14
// baseline (speedup 1.0000x reference)
#include <cuda_runtime.h>
#include <cuda_bf16.h>
#include <math.h>
#include <stdint.h>

#define BATCH 2
#define SEQ   2048
#define MODEL 2048
#define NH    32
#define NKV   8
#define HD    64
#define ROWS  (BATCH*SEQ)   // 4096
#define KVW   (NKV*HD)      // 512

typedef unsigned long long u64;
typedef __nv_bfloat16 bf16;

// ---------------- mma.sync helpers -----------------------------------------
__device__ __forceinline__ uint32_t smem_u32(const void* p) {
    uint32_t a;
    asm("{ .reg .u64 t; cvta.to.shared.u64 t, %1; cvt.u32.u64 %0, t; }" : "=r"(a) : "l"(p));
    return a;
}
__device__ __forceinline__ void ldsm4(uint32_t* r, uint32_t addr) {
    asm volatile("ldmatrix.sync.aligned.m8n8.x4.shared.b16 {%0,%1,%2,%3}, [%4];"
                 : "=r"(r[0]), "=r"(r[1]), "=r"(r[2]), "=r"(r[3]) : "r"(addr));
}
__device__ __forceinline__ void mma_bf16(float* d, const uint32_t* a, const uint32_t* b) {
    asm volatile("mma.sync.aligned.m16n8k16.row.col.f32.bf16.bf16.f32 "
                 "{%0,%1,%2,%3}, {%4,%5,%6,%7}, {%8,%9}, {%0,%1,%2,%3};"
                 : "+f"(d[0]), "+f"(d[1]), "+f"(d[2]), "+f"(d[3])
                 : "r"(a[0]), "r"(a[1]), "r"(a[2]), "r"(a[3]), "r"(b[0]), "r"(b[1]));
}
__device__ __forceinline__ void cp16(uint32_t dst, const void* src) {
    asm volatile("cp.async.cg.shared.global [%0], [%1], 16;" :: "r"(dst), "l"(src));
}
#define CP_COMMIT() asm volatile("cp.async.commit_group;" ::: "memory")
#define CP_WAIT0()  asm volatile("cp.async.wait_group 0;" ::: "memory")
#define CP_WAIT1()  asm volatile("cp.async.wait_group 1;" ::: "memory")

// bf16x2 pack/split: lo float -> bits[15:0], hi float -> bits[31:16]
__device__ __forceinline__ uint32_t pkbf2(float lo, float hi) {
    uint32_t r; asm("cvt.rn.bf16x2.f32 %0, %1, %2;" : "=r"(r) : "f"(hi), "f"(lo)); return r;
}
__device__ __forceinline__ float bflo(uint32_t p) { return __uint_as_float(p << 16); }
__device__ __forceinline__ float bfhi(uint32_t p) { return __uint_as_float(p & 0xffff0000u); }
__device__ __forceinline__ void split2(float f0, float f1, uint32_t& hp, uint32_t& lp) {
    hp = pkbf2(f0, f1);
    lp = pkbf2(f0 - bflo(hp), f1 - bfhi(hp));
}

// ---------------- scratch --------------------------------------------------
__device__ float g_cs[(size_t)SEQ * 32 * 2];

__device__ bf16 g_xh[(size_t)ROWS * MODEL];
__device__ bf16 g_xl[(size_t)ROWS * MODEL];
__device__ bf16 g_Qh[(size_t)ROWS * NH * HD];
__device__ bf16 g_Ql[(size_t)ROWS * NH * HD];
__device__ bf16 g_Kh[(size_t)ROWS * KVW];
__device__ bf16 g_Kl[(size_t)ROWS * KVW];
__device__ bf16 g_Vth[(size_t)BATCH * KVW * SEQ];
__device__ bf16 g_Vtl[(size_t)BATCH * KVW * SEQ];
__device__ bf16 g_Yh[(size_t)ROWS * NH * HD];
__device__ bf16 g_Yl[(size_t)ROWS * NH * HD];
__device__ bf16 g_Wqt_h[(size_t)(NH  * HD) * MODEL];
__device__ bf16 g_Wqt_l[(size_t)(NH  * HD) * MODEL];
__device__ bf16 g_Wkt_h[(size_t)KVW * MODEL];
__device__ bf16 g_Wkt_l[(size_t)KVW * MODEL];
__device__ bf16 g_Wvt_h[(size_t)KVW * MODEL];
__device__ bf16 g_Wvt_l[(size_t)KVW * MODEL];
__device__ bf16 g_Wot_h[(size_t)MODEL * (NH * HD)];
__device__ bf16 g_Wot_l[(size_t)MODEL * (NH * HD)];

// ---------------------------------------------------------------------------
// RoPE cos/sin table
// ---------------------------------------------------------------------------
__global__ __launch_bounds__(256)
void rope_table() {
    int i = blockIdx.x * 256 + threadIdx.x;
    if (i >= SEQ * 32) return;
    int d = i & 31;
    int s = i >> 5;
    double inv = exp2(-(double)d * (13.287712379549448882 / 32.0));
    double ang = (double)s * inv;
    double sd, cd;
    sincos(ang, &sd, &cd);
    g_cs[2 * i + 0] = (float)cd;
    g_cs[2 * i + 1] = (float)sd;
}

// ---------------------------------------------------------------------------
// split fp32 -> (hi, lo) bf16  (x only)
// ---------------------------------------------------------------------------
__global__ __launch_bounds__(256)
void split_rows(const float* __restrict__ X, bf16* __restrict__ H,
                bf16* __restrict__ L, int total) {
    int i = blockIdx.x * 256 + threadIdx.x;
    if (i >= total) return;
    float v = X[i];
    bf16 h = __float2bfloat16(v);
    H[i] = h;
    L[i] = __float2bfloat16(v - __bfloat162float(h));
}

// ---------------------------------------------------------------------------
// ALL weight transposes in one launch
// ---------------------------------------------------------------------------
__global__ __launch_bounds__(256)
void ts_all(const float* __restrict__ Wq, const float* __restrict__ Wk,
            const float* __restrict__ Wv, const float* __restrict__ Wo) {
    __shared__ float tile[32][33];
    const float* W; bf16 *Th, *Tl; int Kd, Nw, nx;
    switch (blockIdx.z) {
        case 0:  W = Wq; Th = g_Wqt_h; Tl = g_Wqt_l; Kd = MODEL;   Nw = NH * HD; nx = 64; break;
        case 1:  W = Wo; Th = g_Wot_h; Tl = g_Wot_l; Kd = NH * HD; Nw = MODEL;   nx = 64; break;
        case 2:  W = Wk; Th = g_Wkt_h; Tl = g_Wkt_l; Kd = MODEL;   Nw = KVW;     nx = 16; break;
        default: W = Wv; Th = g_Wvt_h; Tl = g_Wvt_l; Kd = MODEL;   Nw = KVW;     nx = 16; break;
    }
    if ((int)blockIdx.x >= nx) return;
    int n0 = blockIdx.x * 32, k0 = blockIdx.y * 32;
    int tx = threadIdx.x & 31, ty = threadIdx.x >> 5;
    #pragma unroll
    for (int j = ty; j < 32; j += 8)
        tile[j][tx] = W[(size_t)(k0 + j) * Nw + n0 + tx];
    __syncthreads();
    #pragma unroll
    for (int j = ty; j < 32; j += 8) {
        float v = tile[tx][j];
        bf16 h = __float2bfloat16(v);
        Th[(size_t)(n0 + j) * Kd + k0 + tx] = h;
        Tl[(size_t)(n0 + j) * Kd + k0 + tx] = __float2bfloat16(v - __bfloat162float(h));
    }
}

// ---------------------------------------------------------------------------
// Split-bf16 GEMM core — 256 threads / 8 warps, CTA tile 64x128,
// warp tile 32x32 (cols {c..c+16} U {c+32..c+48} so rope pairs are in-warp),
// 3 CTAs/SM. acc = 32 regs/thread.
// ---------------------------------------------------------------------------
#define GSTAGE 24576
#define GEMM_SMEM (2 * GSTAGE)

__device__ __forceinline__ void g_load_stage(uint32_t sbase,
                                             const bf16* Ah, const bf16* Al,
                                             const bf16* Bh, const bf16* Bl,
                                             int bm, int bn, int kb, int K, int tid) {
    #pragma unroll
    for (int it = 0; it < 2; it++) {          // A: 64 rows x 8 chunks = 512
        int idx = tid + it * 256;
        int r = idx >> 3, c = idx & 7;
        uint32_t dst = sbase + r * 128 + ((c ^ (r & 7)) << 4);
        const bf16* src = (c < 4 ? Ah : Al) + (size_t)(bm + r) * K + kb * 32 + (c & 3) * 8;
        cp16(dst, src);
    }
    #pragma unroll
    for (int it = 0; it < 4; it++) {          // B: 128 rows x 8 chunks = 1024
        int idx = tid + it * 256;
        int r = idx >> 3, c = idx & 7;
        uint32_t dst = sbase + 8192 + r * 128 + ((c ^ (r & 7)) << 4);
        const bf16* src = (c < 4 ? Bh : Bl) + (size_t)(bn + r) * K + kb * 32 + (c & 3) * 8;
        cp16(dst, src);
    }
}

template<int MODE>
__device__ __forceinline__
void gemm_mma_core(const bf16* __restrict__ Ah, const bf16* __restrict__ Al,
                   const bf16* __restrict__ Bh, const bf16* __restrict__ Bl,
                   float* __restrict__ C, bf16* __restrict__ Ch,
                   bf16* __restrict__ Cl, float rscale,
                   int Nt, int K, int bm, int bn) {
    extern __shared__ char smg[];
    const uint32_t sbase = smem_u32(smg);
    const int tid  = threadIdx.x;
    const int lane = tid & 31;
    const int warp = tid >> 5;                 // 0..7
    const int wm   = (warp & 1) * 32;          // m-group
    const int wq   = warp >> 1;                // 0..3 n-group
    const int colbase = (wq >> 1) * 64 + (wq & 1) * 16;

    float acc[2][4][4];                        // [am][an][j], an: 2*(g)+(n8)
    #pragma unroll
    for (int am = 0; am < 2; am++)
        #pragma unroll
        for (int an = 0; an < 4; an++)
            #pragma unroll
            for (int j = 0; j < 4; j++) acc[am][an][j] = 0.f;

    const int KB = K >> 5;
    g_load_stage(sbase, Ah, Al, Bh, Bl, bm, bn, 0, K, tid); CP_COMMIT();

    const int a_row = wm + (lane & 15);
    const int a_kh  = (lane >> 4) & 1;
    const int b_n   = colbase + (lane & 7) + ((lane >> 4) << 3);
    const int b_kh  = (lane >> 3) & 1;

    const int ax7 = a_row & 7;
    const int bx7 = b_n & 7;
    uint32_t Ao[2][2], Bo[2][2];
    #pragma unroll
    for (int h = 0; h < 2; h++) {
        Ao[h][0] = a_row * 128 + (uint32_t)(((h * 2 + a_kh)     ^ ax7) << 4);
        Ao[h][1] = a_row * 128 + (uint32_t)(((h * 2 + a_kh + 4) ^ ax7) << 4);
        Bo[h][0] = 8192 + b_n * 128 + (uint32_t)(((h * 2 + b_kh)     ^ bx7) << 4);
        Bo[h][1] = 8192 + b_n * 128 + (uint32_t)(((h * 2 + b_kh + 4) ^ bx7) << 4);
    }

    for (int t = 0; t < KB; t++) {
        CP_WAIT0();
        __syncthreads();
        if (t + 1 < KB) {
            g_load_stage(sbase + ((t + 1) & 1) * GSTAGE,
                         Ah, Al, Bh, Bl, bm, bn, t + 1, K, tid);
        }
        CP_COMMIT();

        const uint32_t sA = sbase + (t & 1) * GSTAGE;

        #pragma unroll
        for (int h = 0; h < 2; h++) {
            uint32_t bh[2][4], bl[2][4];
            // g=0 at colbase, g=1 at colbase+32 -> +4096 bytes
            #pragma unroll
            for (int g = 0; g < 2; g++) {
                ldsm4(bh[g], sA + Bo[h][0] + g * 4096);
                ldsm4(bl[g], sA + Bo[h][1] + g * 4096);
            }
            #pragma unroll
            for (int am = 0; am < 2; am++) {
                uint32_t ah[4], al[4];
                ldsm4(ah, sA + Ao[h][0] + am * 2048);
                ldsm4(al, sA + Ao[h][1] + am * 2048);
                #pragma unroll
                for (int g = 0; g < 2; g++) {
                    mma_bf16(acc[am][2 * g],     ah, &bh[g][0]);
                    mma_bf16(acc[am][2 * g + 1], ah, &bh[g][2]);
                }
                #pragma unroll
                for (int g = 0; g < 2; g++) {
                    mma_bf16(acc[am][2 * g],     al, &bh[g][0]);
                    mma_bf16(acc[am][2 * g + 1], al, &bh[g][2]);
                }
                #pragma unroll
                for (int g = 0; g < 2; g++) {
                    mma_bf16(acc[am][2 * g],     ah, &bl[g][0]);
                    mma_bf16(acc[am][2 * g + 1], ah, &bl[g][2]);
                }
            }
        }
    }

    // col of accumulator an: colbase + (an>>1)*32 + (an&1)*8 + (lane&3)*2
    if (MODE == 0) {
        #pragma unroll
        for (int am = 0; am < 2; am++) {
            int r0 = bm + wm + am * 16 + (lane >> 2);
            #pragma unroll
            for (int an = 0; an < 4; an++) {
                int col = bn + colbase + (an >> 1) * 32 + (an & 1) * 8 + (lane & 3) * 2;
                *(float2*)&C[(size_t)r0 * Nt + col]       = make_float2(acc[am][an][0], acc[am][an][1]);
                *(float2*)&C[(size_t)(r0 + 8) * Nt + col] = make_float2(acc[am][an][2], acc[am][an][3]);
            }
        }
    } else if (MODE == 1) {
        // rope: an (d in [0,32)) pairs with an+2 (d+32), both in-warp
        #pragma unroll
        for (int am = 0; am < 2; am++) {
            int r0 = bm + wm + am * 16 + (lane >> 2);
            #pragma unroll
            for (int rh = 0; rh < 2; rh++) {
                int row = r0 + rh * 8;
                int s   = row & (SEQ - 1);
                #pragma unroll
                for (int an = 0; an < 2; an++) {
                    int col = bn + colbase + an * 8 + (lane & 3) * 2;
                    int d0  = col & 63;            // in [0,32)
                    float2 cs0 = *(const float2*)&g_cs[2 * (s * 32 + d0)];
                    float2 cs1 = *(const float2*)&g_cs[2 * (s * 32 + d0 + 1)];
                    float v0a = acc[am][an][rh * 2],     v0b = acc[am][an][rh * 2 + 1];
                    float v1a = acc[am][an + 2][rh * 2], v1b = acc[am][an + 2][rh * 2 + 1];
                    float loa = (v0a * cs0.x - v1a * cs0.y) * rscale;
                    float lob = (v0b * cs1.x - v1b * cs1.y) * rscale;
                    float hia = (v1a * cs0.x + v0a * cs0.y) * rscale;
                    float hib = (v1b * cs1.x + v0b * cs1.y) * rscale;
                    uint32_t hp, lp;
                    split2(loa, lob, hp, lp);
                    *(uint32_t*)&Ch[(size_t)row * Nt + col] = hp;
                    *(uint32_t*)&Cl[(size_t)row * Nt + col] = lp;
                    split2(hia, hib, hp, lp);
                    *(uint32_t*)&Ch[(size_t)row * Nt + col + 32] = hp;
                    *(uint32_t*)&Cl[(size_t)row * Nt + col + 32] = lp;
                }
            }
        }
    } else {
        // V transpose + split: out[(b*NKV + col>>6)*64 + (col&63)][s]
        #pragma unroll
        for (int am = 0; am < 2; am++) {
            int r0 = bm + wm + am * 16 + (lane >> 2);
            #pragma unroll
            for (int rh = 0; rh < 2; rh++) {
                int row = r0 + rh * 8;
                int bb  = row >> 11;
                int sl  = row & (SEQ - 1);
                #pragma unroll
                for (int an = 0; an < 4; an++) {
                    int col = bn + colbase + (an >> 1) * 32 + (an & 1) * 8 + (lane & 3) * 2;
                    float va = acc[am][an][rh * 2];
                    float vb = acc[am][an][rh * 2 + 1];
                    size_t o0 = ((size_t)(bb * NKV + (col >> 6)) * 64 + (col & 63)) * SEQ + sl;
                    size_t o1 = o0 + SEQ;
                    bf16 ha = __float2bfloat16(va);
                    Ch[o0] = ha;
                    Cl[o0] = __float2bfloat16(va - __bfloat162float(ha));
                    bf16 hb = __float2bfloat16(vb);
                    Ch[o1] = hb;
                    Cl[o1] = __float2bfloat16(vb - __bfloat162float(hb));
                }
            }
        }
    }
}

// Merged Q+K+V projection: flat 1536-CTA grid.
// ids [0,1024): Q (MODE1, Nt=2048); [1024,1280): K (MODE1, Nt=512);
// [1280,1536): V (MODE2, Nt=512).
__global__ __launch_bounds__(256, 3)
void gemm_qkv(const bf16* __restrict__ xh, const bf16* __restrict__ xl,
              const bf16* __restrict__ Wqh, const bf16* __restrict__ Wql,
              const bf16* __restrict__ Wkh, const bf16* __restrict__ Wkl,
              const bf16* __restrict__ Wvh, const bf16* __restrict__ Wvl,
              bf16* __restrict__ Qh, bf16* __restrict__ Ql,
              bf16* __restrict__ Kh, bf16* __restrict__ Kl,
              bf16* __restrict__ Vth, bf16* __restrict__ Vtl, float qsc) {
    int id = blockIdx.x;
    if (id < 1024) {
        gemm_mma_core<1>(xh, xl, Wqh, Wql, nullptr, Qh, Ql, qsc,
                         NH * HD, MODEL, (id >> 4) * 64, (id & 15) * 128);
    } else if (id < 1280) {
        id -= 1024;
        gemm_mma_core<1>(xh, xl, Wkh, Wkl, nullptr, Kh, Kl, 1.0f,
                         KVW, MODEL, (id >> 2) * 64, (id & 3) * 128);
    } else {
        id -= 1280;
        gemm_mma_core<2>(xh, xl, Wvh, Wvl, nullptr, Vth, Vtl, 0.f,
                         KVW, MODEL, (id >> 2) * 64, (id & 3) * 128);
    }
}

__global__ __launch_bounds__(256, 3)
void gemm_mma(const bf16* __restrict__ Ah, const bf16* __restrict__ Al,
              const bf16* __restrict__ Bh, const bf16* __restrict__ Bl,
              float* __restrict__ C, int Nt, int K) {
    gemm_mma_core<0>(Ah, Al, Bh, Bl, C, nullptr, nullptr, 0.f,
                     Nt, K, blockIdx.y * 64, blockIdx.x * 128);
}

// ---------------------------------------------------------------------------
// Tensor-core flash attention — unchanged (proven R13 version).
// ---------------------------------------------------------------------------
#define QSTR 144
#define FA_STG_SZ 36864
#define FA_SQH 36864
#define FA_SQL 55296
#define FA_SMEM 73728

__device__ __forceinline__
void fa_load_kv(uint32_t sb, const bf16* __restrict__ Khp, const bf16* __restrict__ Klp,
                const bf16* __restrict__ Vhp, const bf16* __restrict__ Vlp,
                size_t krow0, int s0, int tid) {
    #pragma unroll
    for (int i = 0; i < 2; i++) {
        int idx = tid + i * 256;
        int r = idx >> 3, c = idx & 7;
        uint32_t so = r * QSTR + c * 16;
        cp16(sb + so,         Khp + (krow0 + r) * KVW + c * 8);
        cp16(sb + 9216 + so,  Klp + (krow0 + r) * KVW + c * 8);
        cp16(sb + 18432 + so, Vhp + (size_t)r * SEQ + s0 + c * 8);
        cp16(sb + 27648 + so, Vlp + (size_t)r * SEQ + s0 + c * 8);
    }
}

__global__ __launch_bounds__(256, 2)
void flashattn_mma(const bf16* __restrict__ Qh, const bf16* __restrict__ Ql,
                   const bf16* __restrict__ Kh, const bf16* __restrict__ Kl,
                   const bf16* __restrict__ Vth, const bf16* __restrict__ Vtl,
                   bf16* __restrict__ Yh, bf16* __restrict__ Yl) {
    extern __shared__ char sm[];
    const uint32_t base = smem_u32(sm);
    const int tid  = threadIdx.x;
    const int lane = tid & 31;
    const int warp = tid >> 5;
    const int qt   = gridDim.x - 1 - blockIdx.x;
    const int h    = blockIdx.y;
    const int b    = blockIdx.z;
    const int kvh  = h >> 2;
    const int wm   = warp * 16;

    const bf16* Khp = Kh + kvh * 64;
    const bf16* Klp = Kl + kvh * 64;
    const bf16* Vhp = Vth + (size_t)((b * NKV + kvh) * 64) * SEQ;
    const bf16* Vlp = Vtl + (size_t)((b * NKV + kvh) * 64) * SEQ;
    const int njt = 2 * qt + 2;

    {
        size_t qrow0 = (size_t)(b * SEQ + qt * 128);
        int hoff = h * HD;
        #pragma unroll
        for (int i = 0; i < 4; i++) {
            int idx = tid + i * 256;
            int r = idx >> 3, c = idx & 7;
            cp16(base + FA_SQH + r * QSTR + c * 16, Qh + (qrow0 + r) * (NH * HD) + hoff + c * 8);
            cp16(base + FA_SQL + r * QSTR + c * 16, Ql + (qrow0 + r) * (NH * HD) + hoff + c * 8);
        }
    }
    CP_COMMIT();

    fa_load_kv(base, Khp, Klp, Vhp, Vlp, (size_t)b * SEQ, 0, tid);
    CP_COMMIT();

    CP_WAIT1();
    __syncthreads();

    const int a_row = wm + (lane & 15);
    const int a_kh  = (lane >> 4) & 1;
    uint32_t qfh[4][4], qfl[4][4];
    {
        uint32_t qa = base + a_row * QSTR + a_kh * 16;
        #pragma unroll
        for (int kc = 0; kc < 4; kc++) {
            ldsm4(qfh[kc], qa + FA_SQH + kc * 32);
            ldsm4(qfl[kc], qa + FA_SQL + kc * 32);
        }
    }

    const int b_n  = (lane & 7) + ((lane >> 4) << 3);
    const int b_kh = (lane >> 3) & 1;
    const uint32_t KVoff = (uint32_t)(b_n * QSTR + b_kh * 16);

    float m0 = -INFINITY, m1 = -INFINITY, l0 = 0.f, l1 = 0.f;
    float oa[8][4];
    #pragma unroll
    for (int f = 0; f < 8; f++)
        #pragma unroll
        for (int j = 0; j < 4; j++) oa[f][j] = 0.f;

    for (int jt = 0; jt < njt; jt++) {
        CP_WAIT0();
        __syncthreads();
        if (jt + 1 < njt) {
            fa_load_kv(base + ((jt + 1) & 1) * FA_STG_SZ,
                       Khp, Klp, Vhp, Vlp,
                       (size_t)b * SEQ + (jt + 1) * 64, (jt + 1) * 64, tid);
        }
        CP_COMMIT();

        const uint32_t stgKV = base + (jt & 1) * FA_STG_SZ + KVoff;

        float sa[8][4];
        #pragma unroll
        for (int f = 0; f < 8; f++)
            #pragma unroll
            for (int j = 0; j < 4; j++) sa[f][j] = 0.f;

        #pragma unroll
        for (int kc = 0; kc < 4; kc++) {
            #pragma unroll
            for (int g = 0; g < 4; g++) {
                uint32_t kh4[4], kl4[4];
                ldsm4(kh4, stgKV + g * (16 * QSTR) + kc * 32);
                ldsm4(kl4, stgKV + 9216 + g * (16 * QSTR) + kc * 32);
                mma_bf16(sa[2 * g],     qfh[kc], &kh4[0]);
                mma_bf16(sa[2 * g + 1], qfh[kc], &kh4[2]);
                mma_bf16(sa[2 * g],     qfl[kc], &kh4[0]);
                mma_bf16(sa[2 * g + 1], qfl[kc], &kh4[2]);
                mma_bf16(sa[2 * g],     qfh[kc], &kl4[0]);
                mma_bf16(sa[2 * g + 1], qfh[kc], &kl4[2]);
            }
        }

        if (jt * 64 + 63 > qt * 128) {
            int r0g = qt * 128 + wm + (lane >> 2);
            int r1g = r0g + 8;
            #pragma unroll
            for (int f = 0; f < 8; f++) {
                int c0 = jt * 64 + f * 8 + (lane & 3) * 2;
                if (c0 > r0g)     sa[f][0] = -INFINITY;
                if (c0 + 1 > r0g) sa[f][1] = -INFINITY;
                if (c0 > r1g)     sa[f][2] = -INFINITY;
                if (c0 + 1 > r1g) sa[f][3] = -INFINITY;
            }
        }

        float rm0 = -INFINITY, rm1 = -INFINITY;
        #pragma unroll
        for (int f = 0; f < 8; f++) {
            rm0 = fmaxf(rm0, fmaxf(sa[f][0], sa[f][1]));
            rm1 = fmaxf(rm1, fmaxf(sa[f][2], sa[f][3]));
        }
        rm0 = fmaxf(rm0, __shfl_xor_sync(0xffffffffu, rm0, 1));
        rm0 = fmaxf(rm0, __shfl_xor_sync(0xffffffffu, rm0, 2));
        rm1 = fmaxf(rm1, __shfl_xor_sync(0xffffffffu, rm1, 1));
        rm1 = fmaxf(rm1, __shfl_xor_sync(0xffffffffu, rm1, 2));

        float mn0 = fmaxf(m0, rm0), mn1 = fmaxf(m1, rm1);
        float f0 = exp2f(m0 - mn0), f1 = exp2f(m1 - mn1);
        float rs0 = 0.f, rs1 = 0.f;
        #pragma unroll
        for (int f = 0; f < 8; f++) {
            sa[f][0] = exp2f(sa[f][0] - mn0);
            sa[f][1] = exp2f(sa[f][1] - mn0);
            sa[f][2] = exp2f(sa[f][2] - mn1);
            sa[f][3] = exp2f(sa[f][3] - mn1);
            rs0 += sa[f][0] + sa[f][1];
            rs1 += sa[f][2] + sa[f][3];
        }
        rs0 += __shfl_xor_sync(0xffffffffu, rs0, 1);
        rs0 += __shfl_xor_sync(0xffffffffu, rs0, 2);
        rs1 += __shfl_xor_sync(0xffffffffu, rs1, 1);
        rs1 += __shfl_xor_sync(0xffffffffu, rs1, 2);

        l0 = l0 * f0 + rs0;  m0 = mn0;
        l1 = l1 * f1 + rs1;  m1 = mn1;
        #pragma unroll
        for (int f = 0; f < 8; f++) {
            oa[f][0] *= f0; oa[f][1] *= f0;
            oa[f][2] *= f1; oa[f][3] *= f1;
        }

        #pragma unroll
        for (int kc = 0; kc < 4; kc++) {
            uint32_t ah[4], al[4];
            split2(sa[2 * kc][0],     sa[2 * kc][1],     ah[0], al[0]);
            split2(sa[2 * kc][2],     sa[2 * kc][3],     ah[1], al[1]);
            split2(sa[2 * kc + 1][0], sa[2 * kc + 1][1], ah[2], al[2]);
            split2(sa[2 * kc + 1][2], sa[2 * kc + 1][3], ah[3], al[3]);
            #pragma unroll
            for (int g = 0; g < 4; g++) {
                uint32_t vh4[4], vl4[4];
                ldsm4(vh4, stgKV + 18432 + g * (16 * QSTR) + kc * 32);
                ldsm4(vl4, stgKV + 27648 + g * (16 * QSTR) + kc * 32);
                mma_bf16(oa[2 * g],     ah, &vh4[0]);
                mma_bf16(oa[2 * g + 1], ah, &vh4[2]);
                mma_bf16(oa[2 * g],     al, &vh4[0]);
                mma_bf16(oa[2 * g + 1], al, &vh4[2]);
                mma_bf16(oa[2 * g],     ah, &vl4[0]);
                mma_bf16(oa[2 * g + 1], ah, &vl4[2]);
            }
        }
    }

    float inv0 = 1.f / l0, inv1 = 1.f / l1;
    size_t row0 = (size_t)(b * SEQ + qt * 128 + wm + (lane >> 2));
    #pragma unroll
    for (int f = 0; f < 8; f++) {
        int col = h * HD + f * 8 + (lane & 3) * 2;
        uint32_t hp, lp;
        split2(oa[f][0] * inv0, oa[f][1] * inv0, hp, lp);
        *(uint32_t*)&Yh[row0 * (NH * HD) + col] = hp;
        *(uint32_t*)&Yl[row0 * (NH * HD) + col] = lp;
        split2(oa[f][2] * inv1, oa[f][3] * inv1, hp, lp);
        *(uint32_t*)&Yh[(row0 + 8) * (NH * HD) + col] = hp;
        *(uint32_t*)&Yl[(row0 + 8) * (NH * HD) + col] = lp;
    }
}

// ---------------------------------------------------------------------------
extern "C" void kernel_launch(void* const* d_in, const int* in_sizes, int n_in,
                              void* d_out, int out_size) {
    const float* x  = (const float*)d_in[0];
    const float* Wq = (const float*)d_in[1];
    const float* Wk = (const float*)d_in[2];
    const float* Wv = (const float*)d_in[3];
    const float* Wo = (const float*)d_in[4];
    float* out = (float*)d_out;

    bf16 *xh, *xl, *Qh, *Ql, *Kh, *Kl, *Vth, *Vtl, *Yh, *Yl;
    bf16 *Wqh, *Wql, *Wkh, *Wkl, *Wvh, *Wvl, *Woh, *Wol;
    cudaGetSymbolAddress((void**)&xh, g_xh);   cudaGetSymbolAddress((void**)&xl, g_xl);
    cudaGetSymbolAddress((void**)&Qh, g_Qh);   cudaGetSymbolAddress((void**)&Ql, g_Ql);
    cudaGetSymbolAddress((void**)&Kh, g_Kh);   cudaGetSymbolAddress((void**)&Kl, g_Kl);
    cudaGetSymbolAddress((void**)&Vth, g_Vth); cudaGetSymbolAddress((void**)&Vtl, g_Vtl);
    cudaGetSymbolAddress((void**)&Yh, g_Yh);   cudaGetSymbolAddress((void**)&Yl, g_Yl);
    cudaGetSymbolAddress((void**)&Wqh, g_Wqt_h); cudaGetSymbolAddress((void**)&Wql, g_Wqt_l);
    cudaGetSymbolAddress((void**)&Wkh, g_Wkt_h); cudaGetSymbolAddress((void**)&Wkl, g_Wkt_l);
    cudaGetSymbolAddress((void**)&Wvh, g_Wvt_h); cudaGetSymbolAddress((void**)&Wvl, g_Wvt_l);
    cudaGetSymbolAddress((void**)&Woh, g_Wot_h); cudaGetSymbolAddress((void**)&Wol, g_Wot_l);

    dim3 blk(256);
    const float QSC = 0.125f * 1.4426950408889634f;

    rope_table<<<(SEQ * 32 + 255) / 256, blk>>>();
    int totx = ROWS * MODEL;
    split_rows<<<(totx + 255) / 256, blk>>>(x, xh, xl, totx);
    ts_all<<<dim3(64, 64, 4), blk>>>(Wq, Wk, Wv, Wo);

    cudaFuncSetAttribute(gemm_qkv, cudaFuncAttributeMaxDynamicSharedMemorySize, GEMM_SMEM);
    cudaFuncSetAttribute(gemm_mma, cudaFuncAttributeMaxDynamicSharedMemorySize, GEMM_SMEM);

    // merged Q + K + V projections: one 1536-CTA launch
    gemm_qkv<<<1536, blk, GEMM_SMEM>>>(xh, xl, Wqh, Wql, Wkh, Wkl, Wvh, Wvl,
                                       Qh, Ql, Kh, Kl, Vth, Vtl, QSC);

    cudaFuncSetAttribute(flashattn_mma, cudaFuncAttributeMaxDynamicSharedMemorySize, FA_SMEM);
    flashattn_mma<<<dim3(SEQ / 128, NH, BATCH), blk, FA_SMEM>>>(
        Qh, Ql, Kh, Kl, Vth, Vtl, Yh, Yl);

    gemm_mma<<<dim3(MODEL / 128, ROWS / 64), blk, GEMM_SMEM>>>(
        Yh, Yl, Woh, Wol, out, MODEL, MODEL);
}

// round 15
// speedup vs baseline: 1.1758x; 1.1758x over previous
#include <cuda_runtime.h>
#include <cuda_bf16.h>
#include <cuda_fp16.h>
#include <math.h>
#include <stdint.h>

#define BATCH 2
#define SEQ   2048
#define MODEL 2048
#define NH    32
#define NKV   8
#define HD    64
#define ROWS  (BATCH*SEQ)   // 4096
#define KVW   (NKV*HD)      // 512

typedef unsigned long long u64;
typedef __nv_bfloat16 bf16;
typedef __half f16;

// ---------------- mma.sync helpers -----------------------------------------
__device__ __forceinline__ uint32_t smem_u32(const void* p) {
    uint32_t a;
    asm("{ .reg .u64 t; cvta.to.shared.u64 t, %1; cvt.u32.u64 %0, t; }" : "=r"(a) : "l"(p));
    return a;
}
__device__ __forceinline__ void ldsm4(uint32_t* r, uint32_t addr) {
    asm volatile("ldmatrix.sync.aligned.m8n8.x4.shared.b16 {%0,%1,%2,%3}, [%4];"
                 : "=r"(r[0]), "=r"(r[1]), "=r"(r[2]), "=r"(r[3]) : "r"(addr));
}
__device__ __forceinline__ void mma_bf16(float* d, const uint32_t* a, const uint32_t* b) {
    asm volatile("mma.sync.aligned.m16n8k16.row.col.f32.bf16.bf16.f32 "
                 "{%0,%1,%2,%3}, {%4,%5,%6,%7}, {%8,%9}, {%0,%1,%2,%3};"
                 : "+f"(d[0]), "+f"(d[1]), "+f"(d[2]), "+f"(d[3])
                 : "r"(a[0]), "r"(a[1]), "r"(a[2]), "r"(a[3]), "r"(b[0]), "r"(b[1]));
}
__device__ __forceinline__ void mma_f16(float* d, const uint32_t* a, const uint32_t* b) {
    asm volatile("mma.sync.aligned.m16n8k16.row.col.f32.f16.f16.f32 "
                 "{%0,%1,%2,%3}, {%4,%5,%6,%7}, {%8,%9}, {%0,%1,%2,%3};"
                 : "+f"(d[0]), "+f"(d[1]), "+f"(d[2]), "+f"(d[3])
                 : "r"(a[0]), "r"(a[1]), "r"(a[2]), "r"(a[3]), "r"(b[0]), "r"(b[1]));
}
__device__ __forceinline__ void cp16(uint32_t dst, const void* src) {
    asm volatile("cp.async.cg.shared.global [%0], [%1], 16;" :: "r"(dst), "l"(src));
}
#define CP_COMMIT() asm volatile("cp.async.commit_group;" ::: "memory")
#define CP_WAIT0()  asm volatile("cp.async.wait_group 0;" ::: "memory")
#define CP_WAIT1()  asm volatile("cp.async.wait_group 1;" ::: "memory")

// bf16x2 pack/split
__device__ __forceinline__ uint32_t pkbf2(float lo, float hi) {
    uint32_t r; asm("cvt.rn.bf16x2.f32 %0, %1, %2;" : "=r"(r) : "f"(hi), "f"(lo)); return r;
}
__device__ __forceinline__ float bflo(uint32_t p) { return __uint_as_float(p << 16); }
__device__ __forceinline__ float bfhi(uint32_t p) { return __uint_as_float(p & 0xffff0000u); }
__device__ __forceinline__ void split2(float f0, float f1, uint32_t& hp, uint32_t& lp) {
    hp = pkbf2(f0, f1);
    lp = pkbf2(f0 - bflo(hp), f1 - bfhi(hp));
}
// fp16x2 pack/split
__device__ __forceinline__ uint32_t pkhf2(float lo, float hi) {
    uint32_t r; asm("cvt.rn.f16x2.f32 %0, %1, %2;" : "=r"(r) : "f"(hi), "f"(lo)); return r;
}
__device__ __forceinline__ void split2h(float f0, float f1, uint32_t& hp, uint32_t& lp) {
    hp = pkhf2(f0, f1);
    __half2 hv = *(__half2*)&hp;
    lp = pkhf2(f0 - __half2float(hv.x), f1 - __half2float(hv.y));
}

// ---------------- scratch --------------------------------------------------
__device__ float g_cs[(size_t)SEQ * 32 * 2];

__device__ bf16 g_xh[(size_t)ROWS * MODEL];
__device__ bf16 g_xl[(size_t)ROWS * MODEL];
__device__ bf16 g_Qh[(size_t)ROWS * NH * HD];
__device__ bf16 g_Ql[(size_t)ROWS * NH * HD];
__device__ bf16 g_Kh[(size_t)ROWS * KVW];
__device__ bf16 g_Kl[(size_t)ROWS * KVW];
__device__ f16  g_Vt[(size_t)BATCH * KVW * SEQ];   // fp16 hi only, [(b,kvh,d)][s]
__device__ f16  g_Y1[(size_t)ROWS * NH * HD];      // fp16 split of attention out
__device__ f16  g_Y2[(size_t)ROWS * NH * HD];
__device__ bf16 g_Wqt_h[(size_t)(NH  * HD) * MODEL];
__device__ bf16 g_Wqt_l[(size_t)(NH  * HD) * MODEL];
__device__ bf16 g_Wkt_h[(size_t)KVW * MODEL];
__device__ bf16 g_Wkt_l[(size_t)KVW * MODEL];
__device__ bf16 g_Wvt_h[(size_t)KVW * MODEL];
__device__ bf16 g_Wvt_l[(size_t)KVW * MODEL];
__device__ f16  g_Wot[(size_t)MODEL * (NH * HD)];  // fp16 hi only

// ---------------------------------------------------------------------------
// RoPE cos/sin table
// ---------------------------------------------------------------------------
__global__ __launch_bounds__(256)
void rope_table() {
    int i = blockIdx.x * 256 + threadIdx.x;
    if (i >= SEQ * 32) return;
    int d = i & 31;
    int s = i >> 5;
    double inv = exp2(-(double)d * (13.287712379549448882 / 32.0));
    double ang = (double)s * inv;
    double sd, cd;
    sincos(ang, &sd, &cd);
    g_cs[2 * i + 0] = (float)cd;
    g_cs[2 * i + 1] = (float)sd;
}

// ---------------------------------------------------------------------------
// split fp32 -> (hi, lo) bf16  (x only)
// ---------------------------------------------------------------------------
__global__ __launch_bounds__(256)
void split_rows(const float* __restrict__ X, bf16* __restrict__ H,
                bf16* __restrict__ L, int total) {
    int i = blockIdx.x * 256 + threadIdx.x;
    if (i >= total) return;
    float v = X[i];
    bf16 h = __float2bfloat16(v);
    H[i] = h;
    L[i] = __float2bfloat16(v - __bfloat162float(h));
}

// ---------------------------------------------------------------------------
// ALL weight transposes in one launch: z=0 Wq (bf16 pair), 1 Wo (fp16 hi),
// 2 Wk, 3 Wv (bf16 pair)
// ---------------------------------------------------------------------------
__global__ __launch_bounds__(256)
void ts_all(const float* __restrict__ Wq, const float* __restrict__ Wk,
            const float* __restrict__ Wv, const float* __restrict__ Wo) {
    __shared__ float tile[32][33];
    int tx = threadIdx.x & 31, ty = threadIdx.x >> 5;
    int n0 = blockIdx.x * 32, k0 = blockIdx.y * 32;

    if (blockIdx.z == 1) {           // Wo -> fp16 hi only, Kd = NH*HD
        #pragma unroll
        for (int j = ty; j < 32; j += 8)
            tile[j][tx] = Wo[(size_t)(k0 + j) * MODEL + n0 + tx];
        __syncthreads();
        #pragma unroll
        for (int j = ty; j < 32; j += 8)
            g_Wot[(size_t)(n0 + j) * (NH * HD) + k0 + tx] = __float2half(tile[tx][j]);
        return;
    }

    const float* W; bf16 *Th, *Tl; int Nw, nx;
    switch (blockIdx.z) {
        case 0:  W = Wq; Th = g_Wqt_h; Tl = g_Wqt_l; Nw = NH * HD; nx = 64; break;
        case 2:  W = Wk; Th = g_Wkt_h; Tl = g_Wkt_l; Nw = KVW;     nx = 16; break;
        default: W = Wv; Th = g_Wvt_h; Tl = g_Wvt_l; Nw = KVW;     nx = 16; break;
    }
    if ((int)blockIdx.x >= nx) return;
    #pragma unroll
    for (int j = ty; j < 32; j += 8)
        tile[j][tx] = W[(size_t)(k0 + j) * Nw + n0 + tx];
    __syncthreads();
    #pragma unroll
    for (int j = ty; j < 32; j += 8) {
        float v = tile[tx][j];
        bf16 h = __float2bfloat16(v);
        Th[(size_t)(n0 + j) * MODEL + k0 + tx] = h;
        Tl[(size_t)(n0 + j) * MODEL + k0 + tx] = __float2bfloat16(v - __bfloat162float(h));
    }
}

// ---------------------------------------------------------------------------
// Split-bf16 GEMM core (R11 proven geometry): 128 thr, 64x128 tile, 4 CTAs/SM.
// MODE 1: rope+scale+split -> bf16 pair.  MODE 2: V transpose -> fp16 hi only.
// ---------------------------------------------------------------------------
#define GSTAGE 24576
#define GEMM_SMEM (2 * GSTAGE)

__device__ __forceinline__ void g_load_stage(uint32_t sbase,
                                             const bf16* Ah, const bf16* Al,
                                             const bf16* Bh, const bf16* Bl,
                                             int bm, int bn, int kb, int K, int tid) {
    #pragma unroll
    for (int it = 0; it < 4; it++) {
        int idx = tid + it * 128;
        int r = idx >> 3, c = idx & 7;
        uint32_t dst = sbase + r * 128 + ((c ^ (r & 7)) << 4);
        const bf16* src = (c < 4 ? Ah : Al) + (size_t)(bm + r) * K + kb * 32 + (c & 3) * 8;
        cp16(dst, src);
    }
    #pragma unroll
    for (int it = 0; it < 8; it++) {
        int idx = tid + it * 128;
        int r = idx >> 3, c = idx & 7;
        uint32_t dst = sbase + 8192 + r * 128 + ((c ^ (r & 7)) << 4);
        const bf16* src = (c < 4 ? Bh : Bl) + (size_t)(bn + r) * K + kb * 32 + (c & 3) * 8;
        cp16(dst, src);
    }
}

template<int MODE>
__device__ __forceinline__
void gemm_mma_core(const bf16* __restrict__ Ah, const bf16* __restrict__ Al,
                   const bf16* __restrict__ Bh, const bf16* __restrict__ Bl,
                   bf16* __restrict__ Ch, bf16* __restrict__ Cl,
                   f16* __restrict__ Cv, float rscale,
                   int Nt, int K, int bm, int bn) {
    extern __shared__ char smg[];
    const uint32_t sbase = smem_u32(smg);
    const int tid  = threadIdx.x;
    const int lane = tid & 31;
    const int warp = tid >> 5;
    const int wm   = (warp & 1) * 32;
    const int wn   = (warp >> 1) * 64;

    float acc[2][8][4];
    #pragma unroll
    for (int am = 0; am < 2; am++)
        #pragma unroll
        for (int an = 0; an < 8; an++)
            #pragma unroll
            for (int j = 0; j < 4; j++) acc[am][an][j] = 0.f;

    const int KB = K >> 5;
    g_load_stage(sbase,          Ah, Al, Bh, Bl, bm, bn, 0, K, tid); CP_COMMIT();
    g_load_stage(sbase + GSTAGE, Ah, Al, Bh, Bl, bm, bn, 1, K, tid); CP_COMMIT();

    const int a_row  = wm + (lane & 15);
    const int a_kh   = (lane >> 4) & 1;
    const int b_n    = wn + (lane & 7) + ((lane >> 4) << 3);
    const int b_kh   = (lane >> 3) & 1;

    for (int t = 0; t < KB; t++) {
        CP_WAIT1();
        __syncthreads();
        const uint32_t sA = sbase + (t & 1) * GSTAGE;
        const uint32_t sB = sA + 8192;

        #pragma unroll
        for (int h = 0; h < 2; h++) {
            uint32_t bh[4][4], bl[4][4];
            #pragma unroll
            for (int g = 0; g < 4; g++) {
                int n = b_n + g * 16;
                int ch = h * 2 + b_kh;
                ldsm4(bh[g], sB + n * 128 + (((ch)     ^ (n & 7)) << 4));
                ldsm4(bl[g], sB + n * 128 + (((ch + 4) ^ (n & 7)) << 4));
            }
            #pragma unroll
            for (int am = 0; am < 2; am++) {
                int r  = a_row + am * 16;
                int ch = h * 2 + a_kh;
                uint32_t ah[4], al[4];
                ldsm4(ah, sA + r * 128 + (((ch)     ^ (r & 7)) << 4));
                ldsm4(al, sA + r * 128 + (((ch + 4) ^ (r & 7)) << 4));
                #pragma unroll
                for (int g = 0; g < 4; g++) {
                    mma_bf16(acc[am][2 * g],     ah, &bh[g][0]);
                    mma_bf16(acc[am][2 * g + 1], ah, &bh[g][2]);
                }
                #pragma unroll
                for (int g = 0; g < 4; g++) {
                    mma_bf16(acc[am][2 * g],     al, &bh[g][0]);
                    mma_bf16(acc[am][2 * g + 1], al, &bh[g][2]);
                }
                #pragma unroll
                for (int g = 0; g < 4; g++) {
                    mma_bf16(acc[am][2 * g],     ah, &bl[g][0]);
                    mma_bf16(acc[am][2 * g + 1], ah, &bl[g][2]);
                }
            }
        }
        __syncthreads();
        if (t + 2 < KB) {
            g_load_stage(sA, Ah, Al, Bh, Bl, bm, bn, t + 2, K, tid);
        }
        CP_COMMIT();
    }

    if (MODE == 1) {
        // rope + scale + split -> bf16 pair. d pairs with d+32 = an+4.
        #pragma unroll
        for (int am = 0; am < 2; am++) {
            int r0 = bm + wm + am * 16 + (lane >> 2);
            #pragma unroll
            for (int rh = 0; rh < 2; rh++) {
                int row = r0 + rh * 8;
                int s   = row & (SEQ - 1);
                #pragma unroll
                for (int an = 0; an < 4; an++) {
                    int col = bn + wn + an * 8 + (lane & 3) * 2;
                    int d0  = col & 31;
                    float2 cs0 = *(const float2*)&g_cs[2 * (s * 32 + d0)];
                    float2 cs1 = *(const float2*)&g_cs[2 * (s * 32 + d0 + 1)];
                    float v0a = acc[am][an][rh * 2],     v0b = acc[am][an][rh * 2 + 1];
                    float v1a = acc[am][an + 4][rh * 2], v1b = acc[am][an + 4][rh * 2 + 1];
                    float loa = (v0a * cs0.x - v1a * cs0.y) * rscale;
                    float lob = (v0b * cs1.x - v1b * cs1.y) * rscale;
                    float hia = (v1a * cs0.x + v0a * cs0.y) * rscale;
                    float hib = (v1b * cs1.x + v0b * cs1.y) * rscale;
                    uint32_t hp, lp;
                    split2(loa, lob, hp, lp);
                    *(uint32_t*)&Ch[(size_t)row * Nt + col] = hp;
                    *(uint32_t*)&Cl[(size_t)row * Nt + col] = lp;
                    split2(hia, hib, hp, lp);
                    *(uint32_t*)&Ch[(size_t)row * Nt + col + 32] = hp;
                    *(uint32_t*)&Cl[(size_t)row * Nt + col + 32] = lp;
                }
            }
        }
    } else {
        // V transpose -> fp16 hi only: out[(b*NKV + c>>6)*64 + (c&63)][s]
        #pragma unroll
        for (int am = 0; am < 2; am++) {
            int r0 = bm + wm + am * 16 + (lane >> 2);
            #pragma unroll
            for (int rh = 0; rh < 2; rh++) {
                int row = r0 + rh * 8;
                int bb  = row >> 11;
                int sl  = row & (SEQ - 1);
                #pragma unroll
                for (int an = 0; an < 8; an++) {
                    int col = bn + wn + an * 8 + (lane & 3) * 2;
                    size_t o0 = ((size_t)(bb * NKV + (col >> 6)) * 64 + (col & 63)) * SEQ + sl;
                    Cv[o0]       = __float2half(acc[am][an][rh * 2]);
                    Cv[o0 + SEQ] = __float2half(acc[am][an][rh * 2 + 1]);
                }
            }
        }
    }
}

__global__ __launch_bounds__(128, 4)
void gemm_mma_rope(const bf16* __restrict__ Ah, const bf16* __restrict__ Al,
                   const bf16* __restrict__ Bh, const bf16* __restrict__ Bl,
                   bf16* __restrict__ Ch, bf16* __restrict__ Cl,
                   float rscale, int Nt, int K) {
    gemm_mma_core<1>(Ah, Al, Bh, Bl, Ch, Cl, nullptr, rscale,
                     Nt, K, blockIdx.y * 64, blockIdx.x * 128);
}

__global__ __launch_bounds__(128, 4)
void gemm_mma_kv(const bf16* __restrict__ Ah, const bf16* __restrict__ Al,
                 const bf16* __restrict__ Bkh, const bf16* __restrict__ Bkl,
                 const bf16* __restrict__ Bvh, const bf16* __restrict__ Bvl,
                 bf16* __restrict__ Kh, bf16* __restrict__ Kl,
                 f16* __restrict__ Vt, int Nt, int K) {
    if (blockIdx.z == 0)
        gemm_mma_core<1>(Ah, Al, Bkh, Bkl, Kh, Kl, nullptr, 1.0f,
                         Nt, K, blockIdx.y * 64, blockIdx.x * 128);
    else
        gemm_mma_core<2>(Ah, Al, Bvh, Bvl, nullptr, nullptr, Vt, 0.f,
                         Nt, K, blockIdx.y * 64, blockIdx.x * 128);
}

// ---------------------------------------------------------------------------
// fp16 2-term GEMM for Wo: C = (Y1+Y2) @ Wot^T, fp32 out.
// A: Y1/Y2 fp16 in [hi|lo] 128B rows. B: Wot fp16 hi chunks only (lo unused).
// ---------------------------------------------------------------------------
__device__ __forceinline__ void g_load_stage_f16(uint32_t sbase,
                                                 const f16* A1, const f16* A2,
                                                 const f16* B1,
                                                 int bm, int bn, int kb, int K, int tid) {
    #pragma unroll
    for (int it = 0; it < 4; it++) {          // A: 512 chunks
        int idx = tid + it * 128;
        int r = idx >> 3, c = idx & 7;
        uint32_t dst = sbase + r * 128 + ((c ^ (r & 7)) << 4);
        const f16* src = (c < 4 ? A1 : A2) + (size_t)(bm + r) * K + kb * 32 + (c & 3) * 8;
        cp16(dst, src);
    }
    #pragma unroll
    for (int it = 0; it < 4; it++) {          // B hi: 512 chunks (c in 0..3)
        int idx = tid + it * 128;
        int r = idx >> 2, c = idx & 3;
        uint32_t dst = sbase + 8192 + r * 128 + ((c ^ (r & 7)) << 4);
        const f16* src = B1 + (size_t)(bn + r) * K + kb * 32 + c * 8;
        cp16(dst, src);
    }
}

__global__ __launch_bounds__(128, 4)
void gemm_f16_out(const f16* __restrict__ A1, const f16* __restrict__ A2,
                  const f16* __restrict__ B1, float* __restrict__ C,
                  int Nt, int K) {
    extern __shared__ char smg[];
    const uint32_t sbase = smem_u32(smg);
    const int tid  = threadIdx.x;
    const int lane = tid & 31;
    const int warp = tid >> 5;
    const int wm   = (warp & 1) * 32;
    const int wn   = (warp >> 1) * 64;
    const int bm   = blockIdx.y * 64;
    const int bn   = blockIdx.x * 128;

    float acc[2][8][4];
    #pragma unroll
    for (int am = 0; am < 2; am++)
        #pragma unroll
        for (int an = 0; an < 8; an++)
            #pragma unroll
            for (int j = 0; j < 4; j++) acc[am][an][j] = 0.f;

    const int KB = K >> 5;
    g_load_stage_f16(sbase,          A1, A2, B1, bm, bn, 0, K, tid); CP_COMMIT();
    g_load_stage_f16(sbase + GSTAGE, A1, A2, B1, bm, bn, 1, K, tid); CP_COMMIT();

    const int a_row = wm + (lane & 15);
    const int a_kh  = (lane >> 4) & 1;
    const int b_n   = wn + (lane & 7) + ((lane >> 4) << 3);
    const int b_kh  = (lane >> 3) & 1;

    for (int t = 0; t < KB; t++) {
        CP_WAIT1();
        __syncthreads();
        const uint32_t sA = sbase + (t & 1) * GSTAGE;
        const uint32_t sB = sA + 8192;

        #pragma unroll
        for (int h = 0; h < 2; h++) {
            uint32_t bh[4][4];
            #pragma unroll
            for (int g = 0; g < 4; g++) {
                int n = b_n + g * 16;
                int ch = h * 2 + b_kh;
                ldsm4(bh[g], sB + n * 128 + ((ch ^ (n & 7)) << 4));
            }
            #pragma unroll
            for (int am = 0; am < 2; am++) {
                int r  = a_row + am * 16;
                int ch = h * 2 + a_kh;
                uint32_t a1[4], a2[4];
                ldsm4(a1, sA + r * 128 + (((ch)     ^ (r & 7)) << 4));
                ldsm4(a2, sA + r * 128 + (((ch + 4) ^ (r & 7)) << 4));
                #pragma unroll
                for (int g = 0; g < 4; g++) {
                    mma_f16(acc[am][2 * g],     a1, &bh[g][0]);
                    mma_f16(acc[am][2 * g + 1], a1, &bh[g][2]);
                }
                #pragma unroll
                for (int g = 0; g < 4; g++) {
                    mma_f16(acc[am][2 * g],     a2, &bh[g][0]);
                    mma_f16(acc[am][2 * g + 1], a2, &bh[g][2]);
                }
            }
        }
        __syncthreads();
        if (t + 2 < KB) {
            g_load_stage_f16(sA, A1, A2, B1, bm, bn, t + 2, K, tid);
        }
        CP_COMMIT();
    }

    #pragma unroll
    for (int am = 0; am < 2; am++) {
        int r0 = bm + wm + am * 16 + (lane >> 2);
        #pragma unroll
        for (int an = 0; an < 8; an++) {
            int col = bn + wn + an * 8 + (lane & 3) * 2;
            *(float2*)&C[(size_t)r0 * Nt + col]       = make_float2(acc[am][an][0], acc[am][an][1]);
            *(float2*)&C[(size_t)(r0 + 8) * Nt + col] = make_float2(acc[am][an][2], acc[am][an][3]);
        }
    }
}

// ---------------------------------------------------------------------------
// Flash attention: S = QK^T split-bf16 3-term (unchanged numerics);
// P@V = fp16 2-term (P split fp16 pair, V fp16 hi). Y out = fp16 pair.
// stage: Kh 0, Kl 9216, Vh 18432 (size 27648). Q separate region.
// ---------------------------------------------------------------------------
#define QSTR 144
#define FA_STG_SZ 27648
#define FA_SQH 55296
#define FA_SQL 73728
#define FA_SMEM 92160

__device__ __forceinline__
void fa_load_kv(uint32_t sb, const bf16* __restrict__ Khp, const bf16* __restrict__ Klp,
                const f16* __restrict__ Vhp, size_t krow0, int s0, int tid) {
    #pragma unroll
    for (int i = 0; i < 2; i++) {
        int idx = tid + i * 256;
        int r = idx >> 3, c = idx & 7;
        uint32_t so = r * QSTR + c * 16;
        cp16(sb + so,         Khp + (krow0 + r) * KVW + c * 8);
        cp16(sb + 9216 + so,  Klp + (krow0 + r) * KVW + c * 8);
        cp16(sb + 18432 + so, Vhp + (size_t)r * SEQ + s0 + c * 8);
    }
}

__global__ __launch_bounds__(256, 2)
void flashattn_mma(const bf16* __restrict__ Qh, const bf16* __restrict__ Ql,
                   const bf16* __restrict__ Kh, const bf16* __restrict__ Kl,
                   const f16* __restrict__ Vt,
                   f16* __restrict__ Y1, f16* __restrict__ Y2) {
    extern __shared__ char sm[];
    const uint32_t base = smem_u32(sm);
    const int tid  = threadIdx.x;
    const int lane = tid & 31;
    const int warp = tid >> 5;
    const int qt   = gridDim.x - 1 - blockIdx.x;
    const int h    = blockIdx.y;
    const int b    = blockIdx.z;
    const int kvh  = h >> 2;
    const int wm   = warp * 16;

    const bf16* Khp = Kh + kvh * 64;
    const bf16* Klp = Kl + kvh * 64;
    const f16*  Vhp = Vt + (size_t)((b * NKV + kvh) * 64) * SEQ;
    const int njt = 2 * qt + 2;

    // Q cp.async (group 0)
    {
        size_t qrow0 = (size_t)(b * SEQ + qt * 128);
        int hoff = h * HD;
        #pragma unroll
        for (int i = 0; i < 4; i++) {
            int idx = tid + i * 256;
            int r = idx >> 3, c = idx & 7;
            cp16(base + FA_SQH + r * QSTR + c * 16, Qh + (qrow0 + r) * (NH * HD) + hoff + c * 8);
            cp16(base + FA_SQL + r * QSTR + c * 16, Ql + (qrow0 + r) * (NH * HD) + hoff + c * 8);
        }
    }
    CP_COMMIT();
    fa_load_kv(base, Khp, Klp, Vhp, (size_t)b * SEQ, 0, tid);
    CP_COMMIT();
    CP_WAIT1();
    __syncthreads();

    const int a_row = wm + (lane & 15);
    const int a_kh  = (lane >> 4) & 1;
    uint32_t qfh[4][4], qfl[4][4];
    {
        uint32_t qa = base + a_row * QSTR + a_kh * 16;
        #pragma unroll
        for (int kc = 0; kc < 4; kc++) {
            ldsm4(qfh[kc], qa + FA_SQH + kc * 32);
            ldsm4(qfl[kc], qa + FA_SQL + kc * 32);
        }
    }

    const int b_n  = (lane & 7) + ((lane >> 4) << 3);
    const int b_kh = (lane >> 3) & 1;
    const uint32_t KVoff = (uint32_t)(b_n * QSTR + b_kh * 16);

    float m0 = -INFINITY, m1 = -INFINITY, l0 = 0.f, l1 = 0.f;
    float oa[8][4];
    #pragma unroll
    for (int f = 0; f < 8; f++)
        #pragma unroll
        for (int j = 0; j < 4; j++) oa[f][j] = 0.f;

    for (int jt = 0; jt < njt; jt++) {
        __syncthreads();
        if (jt + 1 < njt) {
            fa_load_kv(base + ((jt + 1) & 1) * FA_STG_SZ,
                       Khp, Klp, Vhp,
                       (size_t)b * SEQ + (jt + 1) * 64, (jt + 1) * 64, tid);
        }
        CP_COMMIT();
        CP_WAIT1();
        __syncthreads();

        const uint32_t stgKV = base + (jt & 1) * FA_STG_SZ + KVoff;

        // S = Q @ K^T (3-term bf16, base-2 scaled)
        float sa[8][4];
        #pragma unroll
        for (int f = 0; f < 8; f++)
            #pragma unroll
            for (int j = 0; j < 4; j++) sa[f][j] = 0.f;

        #pragma unroll
        for (int kc = 0; kc < 4; kc++) {
            #pragma unroll
            for (int g = 0; g < 4; g++) {
                uint32_t kh4[4], kl4[4];
                ldsm4(kh4, stgKV + g * (16 * QSTR) + kc * 32);
                ldsm4(kl4, stgKV + 9216 + g * (16 * QSTR) + kc * 32);
                mma_bf16(sa[2 * g],     qfh[kc], &kh4[0]);
                mma_bf16(sa[2 * g + 1], qfh[kc], &kh4[2]);
                mma_bf16(sa[2 * g],     qfl[kc], &kh4[0]);
                mma_bf16(sa[2 * g + 1], qfl[kc], &kh4[2]);
                mma_bf16(sa[2 * g],     qfh[kc], &kl4[0]);
                mma_bf16(sa[2 * g + 1], qfh[kc], &kl4[2]);
            }
        }

        if (jt * 64 + 63 > qt * 128) {
            int r0g = qt * 128 + wm + (lane >> 2);
            int r1g = r0g + 8;
            #pragma unroll
            for (int f = 0; f < 8; f++) {
                int c0 = jt * 64 + f * 8 + (lane & 3) * 2;
                if (c0 > r0g)     sa[f][0] = -INFINITY;
                if (c0 + 1 > r0g) sa[f][1] = -INFINITY;
                if (c0 > r1g)     sa[f][2] = -INFINITY;
                if (c0 + 1 > r1g) sa[f][3] = -INFINITY;
            }
        }

        float rm0 = -INFINITY, rm1 = -INFINITY;
        #pragma unroll
        for (int f = 0; f < 8; f++) {
            rm0 = fmaxf(rm0, fmaxf(sa[f][0], sa[f][1]));
            rm1 = fmaxf(rm1, fmaxf(sa[f][2], sa[f][3]));
        }
        rm0 = fmaxf(rm0, __shfl_xor_sync(0xffffffffu, rm0, 1));
        rm0 = fmaxf(rm0, __shfl_xor_sync(0xffffffffu, rm0, 2));
        rm1 = fmaxf(rm1, __shfl_xor_sync(0xffffffffu, rm1, 1));
        rm1 = fmaxf(rm1, __shfl_xor_sync(0xffffffffu, rm1, 2));

        float mn0 = fmaxf(m0, rm0), mn1 = fmaxf(m1, rm1);
        float f0 = exp2f(m0 - mn0), f1 = exp2f(m1 - mn1);
        float rs0 = 0.f, rs1 = 0.f;
        #pragma unroll
        for (int f = 0; f < 8; f++) {
            sa[f][0] = exp2f(sa[f][0] - mn0);
            sa[f][1] = exp2f(sa[f][1] - mn0);
            sa[f][2] = exp2f(sa[f][2] - mn1);
            sa[f][3] = exp2f(sa[f][3] - mn1);
            rs0 += sa[f][0] + sa[f][1];
            rs1 += sa[f][2] + sa[f][3];
        }
        rs0 += __shfl_xor_sync(0xffffffffu, rs0, 1);
        rs0 += __shfl_xor_sync(0xffffffffu, rs0, 2);
        rs1 += __shfl_xor_sync(0xffffffffu, rs1, 1);
        rs1 += __shfl_xor_sync(0xffffffffu, rs1, 2);

        l0 = l0 * f0 + rs0;  m0 = mn0;
        l1 = l1 * f1 + rs1;  m1 = mn1;
        #pragma unroll
        for (int f = 0; f < 8; f++) {
            oa[f][0] *= f0; oa[f][1] *= f0;
            oa[f][2] *= f1; oa[f][3] *= f1;
        }

        // O += P @ V : fp16 2-term (P pair x V hi)
        #pragma unroll
        for (int kc = 0; kc < 4; kc++) {
            uint32_t p1[4], p2[4];
            split2h(sa[2 * kc][0],     sa[2 * kc][1],     p1[0], p2[0]);
            split2h(sa[2 * kc][2],     sa[2 * kc][3],     p1[1], p2[1]);
            split2h(sa[2 * kc + 1][0], sa[2 * kc + 1][1], p1[2], p2[2]);
            split2h(sa[2 * kc + 1][2], sa[2 * kc + 1][3], p1[3], p2[3]);
            #pragma unroll
            for (int g = 0; g < 4; g++) {
                uint32_t vh4[4];
                ldsm4(vh4, stgKV + 18432 + g * (16 * QSTR) + kc * 32);
                mma_f16(oa[2 * g],     p1, &vh4[0]);
                mma_f16(oa[2 * g + 1], p1, &vh4[2]);
                mma_f16(oa[2 * g],     p2, &vh4[0]);
                mma_f16(oa[2 * g + 1], p2, &vh4[2]);
            }
        }
    }

    // epilogue: normalize, fp16 split, write Y1/Y2
    float inv0 = 1.f / l0, inv1 = 1.f / l1;
    size_t row0 = (size_t)(b * SEQ + qt * 128 + wm + (lane >> 2));
    #pragma unroll
    for (int f = 0; f < 8; f++) {
        int col = h * HD + f * 8 + (lane & 3) * 2;
        uint32_t hp, lp;
        split2h(oa[f][0] * inv0, oa[f][1] * inv0, hp, lp);
        *(uint32_t*)&Y1[row0 * (NH * HD) + col] = hp;
        *(uint32_t*)&Y2[row0 * (NH * HD) + col] = lp;
        split2h(oa[f][2] * inv1, oa[f][3] * inv1, hp, lp);
        *(uint32_t*)&Y1[(row0 + 8) * (NH * HD) + col] = hp;
        *(uint32_t*)&Y2[(row0 + 8) * (NH * HD) + col] = lp;
    }
}

// ---------------------------------------------------------------------------
extern "C" void kernel_launch(void* const* d_in, const int* in_sizes, int n_in,
                              void* d_out, int out_size) {
    const float* x  = (const float*)d_in[0];
    const float* Wq = (const float*)d_in[1];
    const float* Wk = (const float*)d_in[2];
    const float* Wv = (const float*)d_in[3];
    const float* Wo = (const float*)d_in[4];
    float* out = (float*)d_out;

    bf16 *xh, *xl, *Qh, *Ql, *Kh, *Kl;
    bf16 *Wqh, *Wql, *Wkh, *Wkl, *Wvh, *Wvl;
    f16 *Vt, *Y1, *Y2, *Wot;
    cudaGetSymbolAddress((void**)&xh, g_xh);   cudaGetSymbolAddress((void**)&xl, g_xl);
    cudaGetSymbolAddress((void**)&Qh, g_Qh);   cudaGetSymbolAddress((void**)&Ql, g_Ql);
    cudaGetSymbolAddress((void**)&Kh, g_Kh);   cudaGetSymbolAddress((void**)&Kl, g_Kl);
    cudaGetSymbolAddress((void**)&Vt, g_Vt);
    cudaGetSymbolAddress((void**)&Y1, g_Y1);   cudaGetSymbolAddress((void**)&Y2, g_Y2);
    cudaGetSymbolAddress((void**)&Wqh, g_Wqt_h); cudaGetSymbolAddress((void**)&Wql, g_Wqt_l);
    cudaGetSymbolAddress((void**)&Wkh, g_Wkt_h); cudaGetSymbolAddress((void**)&Wkl, g_Wkt_l);
    cudaGetSymbolAddress((void**)&Wvh, g_Wvt_h); cudaGetSymbolAddress((void**)&Wvl, g_Wvt_l);
    cudaGetSymbolAddress((void**)&Wot, g_Wot);

    dim3 blk(256);
    dim3 gblk(128);
    const float QSC = 0.125f * 1.4426950408889634f;

    rope_table<<<(SEQ * 32 + 255) / 256, blk>>>();
    int totx = ROWS * MODEL;
    split_rows<<<(totx + 255) / 256, blk>>>(x, xh, xl, totx);
    ts_all<<<dim3(64, 64, 4), blk>>>(Wq, Wk, Wv, Wo);

    cudaFuncSetAttribute(gemm_mma_rope, cudaFuncAttributeMaxDynamicSharedMemorySize, GEMM_SMEM);
    cudaFuncSetAttribute(gemm_mma_kv, cudaFuncAttributeMaxDynamicSharedMemorySize, GEMM_SMEM);
    cudaFuncSetAttribute(gemm_f16_out, cudaFuncAttributeMaxDynamicSharedMemorySize, GEMM_SMEM);

    gemm_mma_rope<<<dim3((NH * HD) / 128, ROWS / 64), gblk, GEMM_SMEM>>>(
        xh, xl, Wqh, Wql, Qh, Ql, QSC, NH * HD, MODEL);
    gemm_mma_kv<<<dim3(KVW / 128, ROWS / 64, 2), gblk, GEMM_SMEM>>>(
        xh, xl, Wkh, Wkl, Wvh, Wvl, Kh, Kl, Vt, KVW, MODEL);

    cudaFuncSetAttribute(flashattn_mma, cudaFuncAttributeMaxDynamicSharedMemorySize, FA_SMEM);
    flashattn_mma<<<dim3(SEQ / 128, NH, BATCH), blk, FA_SMEM>>>(
        Qh, Ql, Kh, Kl, Vt, Y1, Y2);

    gemm_f16_out<<<dim3(MODEL / 128, ROWS / 64), gblk, GEMM_SMEM>>>(
        Y1, Y2, Wot, out, MODEL, MODEL);
}

// round 16
// speedup vs baseline: 1.3439x; 1.1429x over previous
#include <cuda_runtime.h>
#include <cuda_fp16.h>
#include <math.h>
#include <stdint.h>

#define BATCH 2
#define SEQ   2048
#define MODEL 2048
#define NH    32
#define NKV   8
#define HD    64
#define ROWS  (BATCH*SEQ)   // 4096
#define KVW   (NKV*HD)      // 512

typedef unsigned long long u64;
typedef __half f16;

// ---------------- mma.sync helpers -----------------------------------------
__device__ __forceinline__ uint32_t smem_u32(const void* p) {
    uint32_t a;
    asm("{ .reg .u64 t; cvta.to.shared.u64 t, %1; cvt.u32.u64 %0, t; }" : "=r"(a) : "l"(p));
    return a;
}
__device__ __forceinline__ void ldsm4(uint32_t* r, uint32_t addr) {
    asm volatile("ldmatrix.sync.aligned.m8n8.x4.shared.b16 {%0,%1,%2,%3}, [%4];"
                 : "=r"(r[0]), "=r"(r[1]), "=r"(r[2]), "=r"(r[3]) : "r"(addr));
}
__device__ __forceinline__ void mma_f16(float* d, const uint32_t* a, const uint32_t* b) {
    asm volatile("mma.sync.aligned.m16n8k16.row.col.f32.f16.f16.f32 "
                 "{%0,%1,%2,%3}, {%4,%5,%6,%7}, {%8,%9}, {%0,%1,%2,%3};"
                 : "+f"(d[0]), "+f"(d[1]), "+f"(d[2]), "+f"(d[3])
                 : "r"(a[0]), "r"(a[1]), "r"(a[2]), "r"(a[3]), "r"(b[0]), "r"(b[1]));
}
__device__ __forceinline__ void cp16(uint32_t dst, const void* src) {
    asm volatile("cp.async.cg.shared.global [%0], [%1], 16;" :: "r"(dst), "l"(src));
}
#define CP_COMMIT() asm volatile("cp.async.commit_group;" ::: "memory")
#define CP_WAIT1()  asm volatile("cp.async.wait_group 1;" ::: "memory")

// fp16x2 pack/split
__device__ __forceinline__ uint32_t pkhf2(float lo, float hi) {
    uint32_t r; asm("cvt.rn.f16x2.f32 %0, %1, %2;" : "=r"(r) : "f"(hi), "f"(lo)); return r;
}
__device__ __forceinline__ void split2h(float f0, float f1, uint32_t& hp, uint32_t& lp) {
    hp = pkhf2(f0, f1);
    __half2 hv = *(__half2*)&hp;
    lp = pkhf2(f0 - __half2float(hv.x), f1 - __half2float(hv.y));
}

// ---------------- scratch --------------------------------------------------
__device__ float g_cs[(size_t)SEQ * 32 * 2];

__device__ f16 g_x1[(size_t)ROWS * MODEL];
__device__ f16 g_x2[(size_t)ROWS * MODEL];
__device__ f16 g_Q1[(size_t)ROWS * NH * HD];
__device__ f16 g_Q2[(size_t)ROWS * NH * HD];
__device__ f16 g_K1[(size_t)ROWS * KVW];
__device__ f16 g_K2[(size_t)ROWS * KVW];
__device__ f16 g_Vt[(size_t)BATCH * KVW * SEQ];    // fp16 hi, [(b,kvh,d)][s]
__device__ f16 g_Y1[(size_t)ROWS * NH * HD];
__device__ f16 g_Y2[(size_t)ROWS * NH * HD];
__device__ f16 g_Wqt1[(size_t)(NH * HD) * MODEL];  // 1-term
__device__ f16 g_Wkt1[(size_t)KVW * MODEL];        // 2-term
__device__ f16 g_Wkt2[(size_t)KVW * MODEL];
__device__ f16 g_Wvt1[(size_t)KVW * MODEL];        // 1-term
__device__ f16 g_Wot[(size_t)MODEL * (NH * HD)];   // 1-term

// ---------------------------------------------------------------------------
// RoPE cos/sin table
// ---------------------------------------------------------------------------
__global__ __launch_bounds__(256)
void rope_table() {
    int i = blockIdx.x * 256 + threadIdx.x;
    if (i >= SEQ * 32) return;
    int d = i & 31;
    int s = i >> 5;
    double inv = exp2(-(double)d * (13.287712379549448882 / 32.0));
    double ang = (double)s * inv;
    double sd, cd;
    sincos(ang, &sd, &cd);
    g_cs[2 * i + 0] = (float)cd;
    g_cs[2 * i + 1] = (float)sd;
}

// ---------------------------------------------------------------------------
// split fp32 -> fp16 (hi, lo) pair (x)
// ---------------------------------------------------------------------------
__global__ __launch_bounds__(256)
void split_rows_h(const float* __restrict__ X, f16* __restrict__ H,
                  f16* __restrict__ L, int total) {
    int i = blockIdx.x * 256 + threadIdx.x;
    if (i >= total) return;
    float v = X[i];
    f16 h = __float2half(v);
    H[i] = h;
    L[i] = __float2half(v - __half2float(h));
}

// ---------------------------------------------------------------------------
// Weight transposes: z=0 Wq->f16 hi; z=1 Wo->f16 hi; z=2 Wk->f16 pair;
// z=3 Wv->f16 hi
// ---------------------------------------------------------------------------
__global__ __launch_bounds__(256)
void ts_all(const float* __restrict__ Wq, const float* __restrict__ Wk,
            const float* __restrict__ Wv, const float* __restrict__ Wo) {
    __shared__ float tile[32][33];
    int tx = threadIdx.x & 31, ty = threadIdx.x >> 5;
    int n0 = blockIdx.x * 32, k0 = blockIdx.y * 32;

    if (blockIdx.z == 0) {           // Wq [MODEL, NH*HD] -> [NH*HD, MODEL] hi
        if ((int)blockIdx.x >= 64) return;
        #pragma unroll
        for (int j = ty; j < 32; j += 8)
            tile[j][tx] = Wq[(size_t)(k0 + j) * (NH * HD) + n0 + tx];
        __syncthreads();
        #pragma unroll
        for (int j = ty; j < 32; j += 8)
            g_Wqt1[(size_t)(n0 + j) * MODEL + k0 + tx] = __float2half(tile[tx][j]);
    } else if (blockIdx.z == 1) {    // Wo [NH*HD, MODEL] -> [MODEL, NH*HD] hi
        #pragma unroll
        for (int j = ty; j < 32; j += 8)
            tile[j][tx] = Wo[(size_t)(k0 + j) * MODEL + n0 + tx];
        __syncthreads();
        #pragma unroll
        for (int j = ty; j < 32; j += 8)
            g_Wot[(size_t)(n0 + j) * (NH * HD) + k0 + tx] = __float2half(tile[tx][j]);
    } else if (blockIdx.z == 2) {    // Wk -> f16 pair
        if ((int)blockIdx.x >= 16) return;
        #pragma unroll
        for (int j = ty; j < 32; j += 8)
            tile[j][tx] = Wk[(size_t)(k0 + j) * KVW + n0 + tx];
        __syncthreads();
        #pragma unroll
        for (int j = ty; j < 32; j += 8) {
            float v = tile[tx][j];
            f16 h = __float2half(v);
            g_Wkt1[(size_t)(n0 + j) * MODEL + k0 + tx] = h;
            g_Wkt2[(size_t)(n0 + j) * MODEL + k0 + tx] = __float2half(v - __half2float(h));
        }
    } else {                         // Wv -> f16 hi
        if ((int)blockIdx.x >= 16) return;
        #pragma unroll
        for (int j = ty; j < 32; j += 8)
            tile[j][tx] = Wv[(size_t)(k0 + j) * KVW + n0 + tx];
        __syncthreads();
        #pragma unroll
        for (int j = ty; j < 32; j += 8)
            g_Wvt1[(size_t)(n0 + j) * MODEL + k0 + tx] = __float2half(tile[tx][j]);
    }
}

// ---------------------------------------------------------------------------
// fp16 split GEMM core — 128 thr, CTA tile 64x128, 4 CTAs/SM.
// TERMS=2: C = (A1+A2)@B1^T (2 MMAs/step, B lo not loaded)
// TERMS=3: C = (A1+A2)@(B1+B2)^T minus A2B2 (3 MMAs/step)
// MODE 0: fp32 C.  MODE 1: rope+scale -> f16 pair.  MODE 2: V transpose -> f16.
// ---------------------------------------------------------------------------
#define GSTAGE 24576
#define GEMM_SMEM (2 * GSTAGE)

template<int TERMS>
__device__ __forceinline__ void g_load_stage(uint32_t sbase,
                                             const f16* A1, const f16* A2,
                                             const f16* B1, const f16* B2,
                                             int bm, int bn, int kb, int K, int tid) {
    #pragma unroll
    for (int it = 0; it < 4; it++) {          // A: 64 rows x 8 chunks
        int idx = tid + it * 128;
        int r = idx >> 3, c = idx & 7;
        uint32_t dst = sbase + r * 128 + ((c ^ (r & 7)) << 4);
        const f16* src = (c < 4 ? A1 : A2) + (size_t)(bm + r) * K + kb * 32 + (c & 3) * 8;
        cp16(dst, src);
    }
    if (TERMS == 3) {
        #pragma unroll
        for (int it = 0; it < 8; it++) {      // B: 128 rows x 8 chunks (hi+lo)
            int idx = tid + it * 128;
            int r = idx >> 3, c = idx & 7;
            uint32_t dst = sbase + 8192 + r * 128 + ((c ^ (r & 7)) << 4);
            const f16* src = (c < 4 ? B1 : B2) + (size_t)(bn + r) * K + kb * 32 + (c & 3) * 8;
            cp16(dst, src);
        }
    } else {
        #pragma unroll
        for (int it = 0; it < 4; it++) {      // B: 128 rows x 4 hi chunks
            int idx = tid + it * 128;
            int r = idx >> 2, c = idx & 3;
            uint32_t dst = sbase + 8192 + r * 128 + ((c ^ (r & 7)) << 4);
            const f16* src = B1 + (size_t)(bn + r) * K + kb * 32 + c * 8;
            cp16(dst, src);
        }
    }
}

template<int TERMS, int MODE>
__device__ __forceinline__
void gemm_core(const f16* __restrict__ A1, const f16* __restrict__ A2,
               const f16* __restrict__ B1, const f16* __restrict__ B2,
               float* __restrict__ C, f16* __restrict__ C1,
               f16* __restrict__ C2, float rscale,
               int Nt, int K, int bm, int bn) {
    extern __shared__ char smg[];
    const uint32_t sbase = smem_u32(smg);
    const int tid  = threadIdx.x;
    const int lane = tid & 31;
    const int warp = tid >> 5;
    const int wm   = (warp & 1) * 32;
    const int wn   = (warp >> 1) * 64;

    float acc[2][8][4];
    #pragma unroll
    for (int am = 0; am < 2; am++)
        #pragma unroll
        for (int an = 0; an < 8; an++)
            #pragma unroll
            for (int j = 0; j < 4; j++) acc[am][an][j] = 0.f;

    const int KB = K >> 5;
    g_load_stage<TERMS>(sbase,          A1, A2, B1, B2, bm, bn, 0, K, tid); CP_COMMIT();
    g_load_stage<TERMS>(sbase + GSTAGE, A1, A2, B1, B2, bm, bn, 1, K, tid); CP_COMMIT();

    const int a_row = wm + (lane & 15);
    const int a_kh  = (lane >> 4) & 1;
    const int b_n   = wn + (lane & 7) + ((lane >> 4) << 3);
    const int b_kh  = (lane >> 3) & 1;

    for (int t = 0; t < KB; t++) {
        CP_WAIT1();
        __syncthreads();
        const uint32_t sA = sbase + (t & 1) * GSTAGE;
        const uint32_t sB = sA + 8192;

        #pragma unroll
        for (int h = 0; h < 2; h++) {
            uint32_t bh[4][4], bl[4][4];
            #pragma unroll
            for (int g = 0; g < 4; g++) {
                int n = b_n + g * 16;
                int ch = h * 2 + b_kh;
                ldsm4(bh[g], sB + n * 128 + (((ch) ^ (n & 7)) << 4));
                if (TERMS == 3)
                    ldsm4(bl[g], sB + n * 128 + (((ch + 4) ^ (n & 7)) << 4));
            }
            #pragma unroll
            for (int am = 0; am < 2; am++) {
                int r  = a_row + am * 16;
                int ch = h * 2 + a_kh;
                uint32_t a1[4], a2[4];
                ldsm4(a1, sA + r * 128 + (((ch)     ^ (r & 7)) << 4));
                ldsm4(a2, sA + r * 128 + (((ch + 4) ^ (r & 7)) << 4));
                #pragma unroll
                for (int g = 0; g < 4; g++) {
                    mma_f16(acc[am][2 * g],     a1, &bh[g][0]);
                    mma_f16(acc[am][2 * g + 1], a1, &bh[g][2]);
                }
                #pragma unroll
                for (int g = 0; g < 4; g++) {
                    mma_f16(acc[am][2 * g],     a2, &bh[g][0]);
                    mma_f16(acc[am][2 * g + 1], a2, &bh[g][2]);
                }
                if (TERMS == 3) {
                    #pragma unroll
                    for (int g = 0; g < 4; g++) {
                        mma_f16(acc[am][2 * g],     a1, &bl[g][0]);
                        mma_f16(acc[am][2 * g + 1], a1, &bl[g][2]);
                    }
                }
            }
        }
        __syncthreads();
        if (t + 2 < KB) {
            g_load_stage<TERMS>(sA, A1, A2, B1, B2, bm, bn, t + 2, K, tid);
        }
        CP_COMMIT();
    }

    if (MODE == 0) {
        #pragma unroll
        for (int am = 0; am < 2; am++) {
            int r0 = bm + wm + am * 16 + (lane >> 2);
            #pragma unroll
            for (int an = 0; an < 8; an++) {
                int col = bn + wn + an * 8 + (lane & 3) * 2;
                *(float2*)&C[(size_t)r0 * Nt + col]       = make_float2(acc[am][an][0], acc[am][an][1]);
                *(float2*)&C[(size_t)(r0 + 8) * Nt + col] = make_float2(acc[am][an][2], acc[am][an][3]);
            }
        }
    } else if (MODE == 1) {
        // rope + scale -> fp16 pair. d (col&31) pairs with d+32 (an+4).
        #pragma unroll
        for (int am = 0; am < 2; am++) {
            int r0 = bm + wm + am * 16 + (lane >> 2);
            #pragma unroll
            for (int rh = 0; rh < 2; rh++) {
                int row = r0 + rh * 8;
                int s   = row & (SEQ - 1);
                #pragma unroll
                for (int an = 0; an < 4; an++) {
                    int col = bn + wn + an * 8 + (lane & 3) * 2;
                    int d0  = col & 31;
                    float2 cs0 = *(const float2*)&g_cs[2 * (s * 32 + d0)];
                    float2 cs1 = *(const float2*)&g_cs[2 * (s * 32 + d0 + 1)];
                    float v0a = acc[am][an][rh * 2],     v0b = acc[am][an][rh * 2 + 1];
                    float v1a = acc[am][an + 4][rh * 2], v1b = acc[am][an + 4][rh * 2 + 1];
                    float loa = (v0a * cs0.x - v1a * cs0.y) * rscale;
                    float lob = (v0b * cs1.x - v1b * cs1.y) * rscale;
                    float hia = (v1a * cs0.x + v0a * cs0.y) * rscale;
                    float hib = (v1b * cs1.x + v0b * cs1.y) * rscale;
                    uint32_t hp, lp;
                    split2h(loa, lob, hp, lp);
                    *(uint32_t*)&C1[(size_t)row * Nt + col] = hp;
                    *(uint32_t*)&C2[(size_t)row * Nt + col] = lp;
                    split2h(hia, hib, hp, lp);
                    *(uint32_t*)&C1[(size_t)row * Nt + col + 32] = hp;
                    *(uint32_t*)&C2[(size_t)row * Nt + col + 32] = lp;
                }
            }
        }
    } else {
        // V transpose -> f16 hi: out[(b*NKV + c>>6)*64 + (c&63)][s]
        #pragma unroll
        for (int am = 0; am < 2; am++) {
            int r0 = bm + wm + am * 16 + (lane >> 2);
            #pragma unroll
            for (int rh = 0; rh < 2; rh++) {
                int row = r0 + rh * 8;
                int bb  = row >> 11;
                int sl  = row & (SEQ - 1);
                #pragma unroll
                for (int an = 0; an < 8; an++) {
                    int col = bn + wn + an * 8 + (lane & 3) * 2;
                    size_t o0 = ((size_t)(bb * NKV + (col >> 6)) * 64 + (col & 63)) * SEQ + sl;
                    C1[o0]       = __float2half(acc[am][an][rh * 2]);
                    C1[o0 + SEQ] = __float2half(acc[am][an][rh * 2 + 1]);
                }
            }
        }
    }
}

__global__ __launch_bounds__(128, 4)
void gemm_q(const f16* __restrict__ x1, const f16* __restrict__ x2,
            const f16* __restrict__ Wq1,
            f16* __restrict__ Q1, f16* __restrict__ Q2, float qsc) {
    gemm_core<2, 1>(x1, x2, Wq1, nullptr, nullptr, Q1, Q2, qsc,
                    NH * HD, MODEL, blockIdx.y * 64, blockIdx.x * 128);
}

__global__ __launch_bounds__(128, 4)
void gemm_kv(const f16* __restrict__ x1, const f16* __restrict__ x2,
             const f16* __restrict__ Wk1, const f16* __restrict__ Wk2,
             const f16* __restrict__ Wv1,
             f16* __restrict__ K1, f16* __restrict__ K2, f16* __restrict__ Vt) {
    if (blockIdx.z == 0)
        gemm_core<3, 1>(x1, x2, Wk1, Wk2, nullptr, K1, K2, 1.0f,
                        KVW, MODEL, blockIdx.y * 64, blockIdx.x * 128);
    else
        gemm_core<2, 2>(x1, x2, Wv1, nullptr, nullptr, Vt, nullptr, 0.f,
                        KVW, MODEL, blockIdx.y * 64, blockIdx.x * 128);
}

__global__ __launch_bounds__(128, 4)
void gemm_out(const f16* __restrict__ Y1, const f16* __restrict__ Y2,
              const f16* __restrict__ Wot, float* __restrict__ C) {
    gemm_core<2, 0>(Y1, Y2, Wot, nullptr, C, nullptr, nullptr, 0.f,
                    MODEL, NH * HD, blockIdx.y * 64, blockIdx.x * 128);
}

// ---------------------------------------------------------------------------
// Flash attention: fp16 throughout. S = 3-term (q1k1+q2k1+q1k2),
// PV = 2-term (p1+p2)xVhi. stage: K1 0, K2 9216, V 18432 (27648 total).
// ---------------------------------------------------------------------------
#define QSTR 144
#define FA_STG_SZ 27648
#define FA_SQH 55296
#define FA_SQL 73728
#define FA_SMEM 92160

__device__ __forceinline__
void fa_load_kv(uint32_t sb, const f16* __restrict__ K1p, const f16* __restrict__ K2p,
                const f16* __restrict__ Vhp, size_t krow0, int s0, int tid) {
    #pragma unroll
    for (int i = 0; i < 2; i++) {
        int idx = tid + i * 256;
        int r = idx >> 3, c = idx & 7;
        uint32_t so = r * QSTR + c * 16;
        cp16(sb + so,         K1p + (krow0 + r) * KVW + c * 8);
        cp16(sb + 9216 + so,  K2p + (krow0 + r) * KVW + c * 8);
        cp16(sb + 18432 + so, Vhp + (size_t)r * SEQ + s0 + c * 8);
    }
}

__global__ __launch_bounds__(256, 2)
void flashattn_mma(const f16* __restrict__ Q1, const f16* __restrict__ Q2,
                   const f16* __restrict__ K1, const f16* __restrict__ K2,
                   const f16* __restrict__ Vt,
                   f16* __restrict__ Y1, f16* __restrict__ Y2) {
    extern __shared__ char sm[];
    const uint32_t base = smem_u32(sm);
    const int tid  = threadIdx.x;
    const int lane = tid & 31;
    const int warp = tid >> 5;
    const int qt   = gridDim.x - 1 - blockIdx.x;
    const int h    = blockIdx.y;
    const int b    = blockIdx.z;
    const int kvh  = h >> 2;
    const int wm   = warp * 16;

    const f16* K1p = K1 + kvh * 64;
    const f16* K2p = K2 + kvh * 64;
    const f16* Vhp = Vt + (size_t)((b * NKV + kvh) * 64) * SEQ;
    const int njt = 2 * qt + 2;

    // Q cp.async (group 0)
    {
        size_t qrow0 = (size_t)(b * SEQ + qt * 128);
        int hoff = h * HD;
        #pragma unroll
        for (int i = 0; i < 4; i++) {
            int idx = tid + i * 256;
            int r = idx >> 3, c = idx & 7;
            cp16(base + FA_SQH + r * QSTR + c * 16, Q1 + (qrow0 + r) * (NH * HD) + hoff + c * 8);
            cp16(base + FA_SQL + r * QSTR + c * 16, Q2 + (qrow0 + r) * (NH * HD) + hoff + c * 8);
        }
    }
    CP_COMMIT();
    fa_load_kv(base, K1p, K2p, Vhp, (size_t)b * SEQ, 0, tid);
    CP_COMMIT();
    CP_WAIT1();
    __syncthreads();

    const int a_row = wm + (lane & 15);
    const int a_kh  = (lane >> 4) & 1;
    uint32_t qf1[4][4], qf2[4][4];
    {
        uint32_t qa = base + a_row * QSTR + a_kh * 16;
        #pragma unroll
        for (int kc = 0; kc < 4; kc++) {
            ldsm4(qf1[kc], qa + FA_SQH + kc * 32);
            ldsm4(qf2[kc], qa + FA_SQL + kc * 32);
        }
    }

    const int b_n  = (lane & 7) + ((lane >> 4) << 3);
    const int b_kh = (lane >> 3) & 1;
    const uint32_t KVoff = (uint32_t)(b_n * QSTR + b_kh * 16);

    float m0 = -INFINITY, m1 = -INFINITY, l0 = 0.f, l1 = 0.f;
    float oa[8][4];
    #pragma unroll
    for (int f = 0; f < 8; f++)
        #pragma unroll
        for (int j = 0; j < 4; j++) oa[f][j] = 0.f;

    for (int jt = 0; jt < njt; jt++) {
        __syncthreads();
        if (jt + 1 < njt) {
            fa_load_kv(base + ((jt + 1) & 1) * FA_STG_SZ,
                       K1p, K2p, Vhp,
                       (size_t)b * SEQ + (jt + 1) * 64, (jt + 1) * 64, tid);
        }
        CP_COMMIT();
        CP_WAIT1();
        __syncthreads();

        const uint32_t stgKV = base + (jt & 1) * FA_STG_SZ + KVoff;

        // S = Q @ K^T (fp16 3-term, base-2 scaled)
        float sa[8][4];
        #pragma unroll
        for (int f = 0; f < 8; f++)
            #pragma unroll
            for (int j = 0; j < 4; j++) sa[f][j] = 0.f;

        #pragma unroll
        for (int kc = 0; kc < 4; kc++) {
            #pragma unroll
            for (int g = 0; g < 4; g++) {
                uint32_t k14[4], k24[4];
                ldsm4(k14, stgKV + g * (16 * QSTR) + kc * 32);
                ldsm4(k24, stgKV + 9216 + g * (16 * QSTR) + kc * 32);
                mma_f16(sa[2 * g],     qf1[kc], &k14[0]);
                mma_f16(sa[2 * g + 1], qf1[kc], &k14[2]);
                mma_f16(sa[2 * g],     qf2[kc], &k14[0]);
                mma_f16(sa[2 * g + 1], qf2[kc], &k14[2]);
                mma_f16(sa[2 * g],     qf1[kc], &k24[0]);
                mma_f16(sa[2 * g + 1], qf1[kc], &k24[2]);
            }
        }

        if (jt * 64 + 63 > qt * 128) {
            int r0g = qt * 128 + wm + (lane >> 2);
            int r1g = r0g + 8;
            #pragma unroll
            for (int f = 0; f < 8; f++) {
                int c0 = jt * 64 + f * 8 + (lane & 3) * 2;
                if (c0 > r0g)     sa[f][0] = -INFINITY;
                if (c0 + 1 > r0g) sa[f][1] = -INFINITY;
                if (c0 > r1g)     sa[f][2] = -INFINITY;
                if (c0 + 1 > r1g) sa[f][3] = -INFINITY;
            }
        }

        float rm0 = -INFINITY, rm1 = -INFINITY;
        #pragma unroll
        for (int f = 0; f < 8; f++) {
            rm0 = fmaxf(rm0, fmaxf(sa[f][0], sa[f][1]));
            rm1 = fmaxf(rm1, fmaxf(sa[f][2], sa[f][3]));
        }
        rm0 = fmaxf(rm0, __shfl_xor_sync(0xffffffffu, rm0, 1));
        rm0 = fmaxf(rm0, __shfl_xor_sync(0xffffffffu, rm0, 2));
        rm1 = fmaxf(rm1, __shfl_xor_sync(0xffffffffu, rm1, 1));
        rm1 = fmaxf(rm1, __shfl_xor_sync(0xffffffffu, rm1, 2));

        float mn0 = fmaxf(m0, rm0), mn1 = fmaxf(m1, rm1);
        float f0 = exp2f(m0 - mn0), f1 = exp2f(m1 - mn1);
        float rs0 = 0.f, rs1 = 0.f;
        #pragma unroll
        for (int f = 0; f < 8; f++) {
            sa[f][0] = exp2f(sa[f][0] - mn0);
            sa[f][1] = exp2f(sa[f][1] - mn0);
            sa[f][2] = exp2f(sa[f][2] - mn1);
            sa[f][3] = exp2f(sa[f][3] - mn1);
            rs0 += sa[f][0] + sa[f][1];
            rs1 += sa[f][2] + sa[f][3];
        }
        rs0 += __shfl_xor_sync(0xffffffffu, rs0, 1);
        rs0 += __shfl_xor_sync(0xffffffffu, rs0, 2);
        rs1 += __shfl_xor_sync(0xffffffffu, rs1, 1);
        rs1 += __shfl_xor_sync(0xffffffffu, rs1, 2);

        l0 = l0 * f0 + rs0;  m0 = mn0;
        l1 = l1 * f1 + rs1;  m1 = mn1;
        #pragma unroll
        for (int f = 0; f < 8; f++) {
            oa[f][0] *= f0; oa[f][1] *= f0;
            oa[f][2] *= f1; oa[f][3] *= f1;
        }

        // O += P @ V (fp16 2-term P x V hi)
        #pragma unroll
        for (int kc = 0; kc < 4; kc++) {
            uint32_t p1[4], p2[4];
            split2h(sa[2 * kc][0],     sa[2 * kc][1],     p1[0], p2[0]);
            split2h(sa[2 * kc][2],     sa[2 * kc][3],     p1[1], p2[1]);
            split2h(sa[2 * kc + 1][0], sa[2 * kc + 1][1], p1[2], p2[2]);
            split2h(sa[2 * kc + 1][2], sa[2 * kc + 1][3], p1[3], p2[3]);
            #pragma unroll
            for (int g = 0; g < 4; g++) {
                uint32_t vh4[4];
                ldsm4(vh4, stgKV + 18432 + g * (16 * QSTR) + kc * 32);
                mma_f16(oa[2 * g],     p1, &vh4[0]);
                mma_f16(oa[2 * g + 1], p1, &vh4[2]);
                mma_f16(oa[2 * g],     p2, &vh4[0]);
                mma_f16(oa[2 * g + 1], p2, &vh4[2]);
            }
        }
    }

    float inv0 = 1.f / l0, inv1 = 1.f / l1;
    size_t row0 = (size_t)(b * SEQ + qt * 128 + wm + (lane >> 2));
    #pragma unroll
    for (int f = 0; f < 8; f++) {
        int col = h * HD + f * 8 + (lane & 3) * 2;
        uint32_t hp, lp;
        split2h(oa[f][0] * inv0, oa[f][1] * inv0, hp, lp);
        *(uint32_t*)&Y1[row0 * (NH * HD) + col] = hp;
        *(uint32_t*)&Y2[row0 * (NH * HD) + col] = lp;
        split2h(oa[f][2] * inv1, oa[f][3] * inv1, hp, lp);
        *(uint32_t*)&Y1[(row0 + 8) * (NH * HD) + col] = hp;
        *(uint32_t*)&Y2[(row0 + 8) * (NH * HD) + col] = lp;
    }
}

// ---------------------------------------------------------------------------
extern "C" void kernel_launch(void* const* d_in, const int* in_sizes, int n_in,
                              void* d_out, int out_size) {
    const float* x  = (const float*)d_in[0];
    const float* Wq = (const float*)d_in[1];
    const float* Wk = (const float*)d_in[2];
    const float* Wv = (const float*)d_in[3];
    const float* Wo = (const float*)d_in[4];
    float* out = (float*)d_out;

    f16 *x1, *x2, *Q1, *Q2, *K1, *K2, *Vt, *Y1, *Y2;
    f16 *Wq1, *Wk1, *Wk2, *Wv1, *Wot;
    cudaGetSymbolAddress((void**)&x1, g_x1);   cudaGetSymbolAddress((void**)&x2, g_x2);
    cudaGetSymbolAddress((void**)&Q1, g_Q1);   cudaGetSymbolAddress((void**)&Q2, g_Q2);
    cudaGetSymbolAddress((void**)&K1, g_K1);   cudaGetSymbolAddress((void**)&K2, g_K2);
    cudaGetSymbolAddress((void**)&Vt, g_Vt);
    cudaGetSymbolAddress((void**)&Y1, g_Y1);   cudaGetSymbolAddress((void**)&Y2, g_Y2);
    cudaGetSymbolAddress((void**)&Wq1, g_Wqt1);
    cudaGetSymbolAddress((void**)&Wk1, g_Wkt1); cudaGetSymbolAddress((void**)&Wk2, g_Wkt2);
    cudaGetSymbolAddress((void**)&Wv1, g_Wvt1);
    cudaGetSymbolAddress((void**)&Wot, g_Wot);

    dim3 blk(256);
    dim3 gblk(128);
    const float QSC = 0.125f * 1.4426950408889634f;

    rope_table<<<(SEQ * 32 + 255) / 256, blk>>>();
    int totx = ROWS * MODEL;
    split_rows_h<<<(totx + 255) / 256, blk>>>(x, x1, x2, totx);
    ts_all<<<dim3(64, 64, 4), blk>>>(Wq, Wk, Wv, Wo);

    cudaFuncSetAttribute(gemm_q,   cudaFuncAttributeMaxDynamicSharedMemorySize, GEMM_SMEM);
    cudaFuncSetAttribute(gemm_kv,  cudaFuncAttributeMaxDynamicSharedMemorySize, GEMM_SMEM);
    cudaFuncSetAttribute(gemm_out, cudaFuncAttributeMaxDynamicSharedMemorySize, GEMM_SMEM);

    gemm_q<<<dim3((NH * HD) / 128, ROWS / 64), gblk, GEMM_SMEM>>>(
        x1, x2, Wq1, Q1, Q2, QSC);
    gemm_kv<<<dim3(KVW / 128, ROWS / 64, 2), gblk, GEMM_SMEM>>>(
        x1, x2, Wk1, Wk2, Wv1, K1, K2, Vt);

    cudaFuncSetAttribute(flashattn_mma, cudaFuncAttributeMaxDynamicSharedMemorySize, FA_SMEM);
    flashattn_mma<<<dim3(SEQ / 128, NH, BATCH), blk, FA_SMEM>>>(
        Q1, Q2, K1, K2, Vt, Y1, Y2);

    gemm_out<<<dim3(MODEL / 128, ROWS / 64), gblk, GEMM_SMEM>>>(
        Y1, Y2, Wot, out);
}

// round 17
// speedup vs baseline: 1.5383x; 1.1447x over previous
#include <cuda_runtime.h>
#include <cuda_fp16.h>
#include <math.h>
#include <stdint.h>

#define BATCH 2
#define SEQ   2048
#define MODEL 2048
#define NH    32
#define NKV   8
#define HD    64
#define ROWS  (BATCH*SEQ)   // 4096
#define KVW   (NKV*HD)      // 512

typedef unsigned long long u64;
typedef __half f16;

// ---------------- mma.sync helpers -----------------------------------------
__device__ __forceinline__ uint32_t smem_u32(const void* p) {
    uint32_t a;
    asm("{ .reg .u64 t; cvta.to.shared.u64 t, %1; cvt.u32.u64 %0, t; }" : "=r"(a) : "l"(p));
    return a;
}
__device__ __forceinline__ void ldsm4(uint32_t* r, uint32_t addr) {
    asm volatile("ldmatrix.sync.aligned.m8n8.x4.shared.b16 {%0,%1,%2,%3}, [%4];"
                 : "=r"(r[0]), "=r"(r[1]), "=r"(r[2]), "=r"(r[3]) : "r"(addr));
}
__device__ __forceinline__ void mma_f16(float* d, const uint32_t* a, const uint32_t* b) {
    asm volatile("mma.sync.aligned.m16n8k16.row.col.f32.f16.f16.f32 "
                 "{%0,%1,%2,%3}, {%4,%5,%6,%7}, {%8,%9}, {%0,%1,%2,%3};"
                 : "+f"(d[0]), "+f"(d[1]), "+f"(d[2]), "+f"(d[3])
                 : "r"(a[0]), "r"(a[1]), "r"(a[2]), "r"(a[3]), "r"(b[0]), "r"(b[1]));
}
__device__ __forceinline__ void cp16(uint32_t dst, const void* src) {
    asm volatile("cp.async.cg.shared.global [%0], [%1], 16;" :: "r"(dst), "l"(src));
}
#define CP_COMMIT() asm volatile("cp.async.commit_group;" ::: "memory")
#define CP_WAIT1()  asm volatile("cp.async.wait_group 1;" ::: "memory")

// fp16x2 pack/split
__device__ __forceinline__ uint32_t pkhf2(float lo, float hi) {
    uint32_t r; asm("cvt.rn.f16x2.f32 %0, %1, %2;" : "=r"(r) : "f"(hi), "f"(lo)); return r;
}
__device__ __forceinline__ void split2h(float f0, float f1, uint32_t& hp, uint32_t& lp) {
    hp = pkhf2(f0, f1);
    __half2 hv = *(__half2*)&hp;
    lp = pkhf2(f0 - __half2float(hv.x), f1 - __half2float(hv.y));
}

// ---------------- scratch --------------------------------------------------
__device__ float g_cs[(size_t)SEQ * 32 * 2];

__device__ f16 g_x1[(size_t)ROWS * MODEL];
__device__ f16 g_x2[(size_t)ROWS * MODEL];
__device__ f16 g_Q1[(size_t)ROWS * NH * HD];
__device__ f16 g_Q2[(size_t)ROWS * NH * HD];
__device__ f16 g_K1[(size_t)ROWS * KVW];
__device__ f16 g_K2[(size_t)ROWS * KVW];
__device__ f16 g_Vt[(size_t)BATCH * KVW * SEQ];    // fp16 hi, [(b,kvh,d)][s]
__device__ f16 g_Y1[(size_t)ROWS * NH * HD];
__device__ f16 g_Wqt1[(size_t)(NH * HD) * MODEL];  // 1-term
__device__ f16 g_Wkt1[(size_t)KVW * MODEL];        // 2-term
__device__ f16 g_Wkt2[(size_t)KVW * MODEL];
__device__ f16 g_Wvt1[(size_t)KVW * MODEL];        // 1-term
__device__ f16 g_Wot[(size_t)MODEL * (NH * HD)];   // 1-term

// ---------------------------------------------------------------------------
// RoPE cos/sin table
// ---------------------------------------------------------------------------
__global__ __launch_bounds__(256)
void rope_table() {
    int i = blockIdx.x * 256 + threadIdx.x;
    if (i >= SEQ * 32) return;
    int d = i & 31;
    int s = i >> 5;
    double inv = exp2(-(double)d * (13.287712379549448882 / 32.0));
    double ang = (double)s * inv;
    double sd, cd;
    sincos(ang, &sd, &cd);
    g_cs[2 * i + 0] = (float)cd;
    g_cs[2 * i + 1] = (float)sd;
}

// ---------------------------------------------------------------------------
// split fp32 -> fp16 (hi, lo) pair (x)
// ---------------------------------------------------------------------------
__global__ __launch_bounds__(256)
void split_rows_h(const float* __restrict__ X, f16* __restrict__ H,
                  f16* __restrict__ L, int total) {
    int i = blockIdx.x * 256 + threadIdx.x;
    if (i >= total) return;
    float v = X[i];
    f16 h = __float2half(v);
    H[i] = h;
    L[i] = __float2half(v - __half2float(h));
}

// ---------------------------------------------------------------------------
// Weight transposes: z=0 Wq->f16 hi; z=1 Wo->f16 hi; z=2 Wk->f16 pair;
// z=3 Wv->f16 hi
// ---------------------------------------------------------------------------
__global__ __launch_bounds__(256)
void ts_all(const float* __restrict__ Wq, const float* __restrict__ Wk,
            const float* __restrict__ Wv, const float* __restrict__ Wo) {
    __shared__ float tile[32][33];
    int tx = threadIdx.x & 31, ty = threadIdx.x >> 5;
    int n0 = blockIdx.x * 32, k0 = blockIdx.y * 32;

    if (blockIdx.z == 0) {
        if ((int)blockIdx.x >= 64) return;
        #pragma unroll
        for (int j = ty; j < 32; j += 8)
            tile[j][tx] = Wq[(size_t)(k0 + j) * (NH * HD) + n0 + tx];
        __syncthreads();
        #pragma unroll
        for (int j = ty; j < 32; j += 8)
            g_Wqt1[(size_t)(n0 + j) * MODEL + k0 + tx] = __float2half(tile[tx][j]);
    } else if (blockIdx.z == 1) {
        #pragma unroll
        for (int j = ty; j < 32; j += 8)
            tile[j][tx] = Wo[(size_t)(k0 + j) * MODEL + n0 + tx];
        __syncthreads();
        #pragma unroll
        for (int j = ty; j < 32; j += 8)
            g_Wot[(size_t)(n0 + j) * (NH * HD) + k0 + tx] = __float2half(tile[tx][j]);
    } else if (blockIdx.z == 2) {
        if ((int)blockIdx.x >= 16) return;
        #pragma unroll
        for (int j = ty; j < 32; j += 8)
            tile[j][tx] = Wk[(size_t)(k0 + j) * KVW + n0 + tx];
        __syncthreads();
        #pragma unroll
        for (int j = ty; j < 32; j += 8) {
            float v = tile[tx][j];
            f16 h = __float2half(v);
            g_Wkt1[(size_t)(n0 + j) * MODEL + k0 + tx] = h;
            g_Wkt2[(size_t)(n0 + j) * MODEL + k0 + tx] = __float2half(v - __half2float(h));
        }
    } else {
        if ((int)blockIdx.x >= 16) return;
        #pragma unroll
        for (int j = ty; j < 32; j += 8)
            tile[j][tx] = Wv[(size_t)(k0 + j) * KVW + n0 + tx];
        __syncthreads();
        #pragma unroll
        for (int j = ty; j < 32; j += 8)
            g_Wvt1[(size_t)(n0 + j) * MODEL + k0 + tx] = __float2half(tile[tx][j]);
    }
}

// ---------------------------------------------------------------------------
// fp16 split GEMM core — 128 thr, CTA tile 64x128, 4 CTAs/SM.
// TERMS=1: C = A1@B1^T.  TERMS=2: (A1+A2)@B1^T.  TERMS=3: +A1@B2^T.
// MODE 0: fp32 C.  MODE 1: rope+scale -> f16 pair.  MODE 2: V transpose.
// ---------------------------------------------------------------------------
#define GSTAGE 24576
#define GEMM_SMEM (2 * GSTAGE)

template<int TERMS>
__device__ __forceinline__ void g_load_stage(uint32_t sbase,
                                             const f16* A1, const f16* A2,
                                             const f16* B1, const f16* B2,
                                             int bm, int bn, int kb, int K, int tid) {
    if (TERMS >= 2) {
        #pragma unroll
        for (int it = 0; it < 4; it++) {          // A: hi+lo, 512 chunks
            int idx = tid + it * 128;
            int r = idx >> 3, c = idx & 7;
            uint32_t dst = sbase + r * 128 + ((c ^ (r & 7)) << 4);
            const f16* src = (c < 4 ? A1 : A2) + (size_t)(bm + r) * K + kb * 32 + (c & 3) * 8;
            cp16(dst, src);
        }
    } else {
        #pragma unroll
        for (int it = 0; it < 2; it++) {          // A: hi only, 256 chunks
            int idx = tid + it * 128;
            int r = idx >> 2, c = idx & 3;
            uint32_t dst = sbase + r * 128 + ((c ^ (r & 7)) << 4);
            const f16* src = A1 + (size_t)(bm + r) * K + kb * 32 + c * 8;
            cp16(dst, src);
        }
    }
    if (TERMS == 3) {
        #pragma unroll
        for (int it = 0; it < 8; it++) {          // B: hi+lo, 1024 chunks
            int idx = tid + it * 128;
            int r = idx >> 3, c = idx & 7;
            uint32_t dst = sbase + 8192 + r * 128 + ((c ^ (r & 7)) << 4);
            const f16* src = (c < 4 ? B1 : B2) + (size_t)(bn + r) * K + kb * 32 + (c & 3) * 8;
            cp16(dst, src);
        }
    } else {
        #pragma unroll
        for (int it = 0; it < 4; it++) {          // B: hi only, 512 chunks
            int idx = tid + it * 128;
            int r = idx >> 2, c = idx & 3;
            uint32_t dst = sbase + 8192 + r * 128 + ((c ^ (r & 7)) << 4);
            const f16* src = B1 + (size_t)(bn + r) * K + kb * 32 + c * 8;
            cp16(dst, src);
        }
    }
}

template<int TERMS, int MODE>
__device__ __forceinline__
void gemm_core(const f16* __restrict__ A1, const f16* __restrict__ A2,
               const f16* __restrict__ B1, const f16* __restrict__ B2,
               float* __restrict__ C, f16* __restrict__ C1,
               f16* __restrict__ C2, float rscale,
               int Nt, int K, int bm, int bn) {
    extern __shared__ char smg[];
    const uint32_t sbase = smem_u32(smg);
    const int tid  = threadIdx.x;
    const int lane = tid & 31;
    const int warp = tid >> 5;
    const int wm   = (warp & 1) * 32;
    const int wn   = (warp >> 1) * 64;

    float acc[2][8][4];
    #pragma unroll
    for (int am = 0; am < 2; am++)
        #pragma unroll
        for (int an = 0; an < 8; an++)
            #pragma unroll
            for (int j = 0; j < 4; j++) acc[am][an][j] = 0.f;

    const int KB = K >> 5;
    g_load_stage<TERMS>(sbase,          A1, A2, B1, B2, bm, bn, 0, K, tid); CP_COMMIT();
    g_load_stage<TERMS>(sbase + GSTAGE, A1, A2, B1, B2, bm, bn, 1, K, tid); CP_COMMIT();

    const int a_row = wm + (lane & 15);
    const int a_kh  = (lane >> 4) & 1;
    const int b_n   = wn + (lane & 7) + ((lane >> 4) << 3);
    const int b_kh  = (lane >> 3) & 1;

    for (int t = 0; t < KB; t++) {
        CP_WAIT1();
        __syncthreads();
        const uint32_t sA = sbase + (t & 1) * GSTAGE;
        const uint32_t sB = sA + 8192;

        #pragma unroll
        for (int h = 0; h < 2; h++) {
            uint32_t bh[4][4], bl[4][4];
            #pragma unroll
            for (int g = 0; g < 4; g++) {
                int n = b_n + g * 16;
                int ch = h * 2 + b_kh;
                ldsm4(bh[g], sB + n * 128 + (((ch) ^ (n & 7)) << 4));
                if (TERMS == 3)
                    ldsm4(bl[g], sB + n * 128 + (((ch + 4) ^ (n & 7)) << 4));
            }
            #pragma unroll
            for (int am = 0; am < 2; am++) {
                int r  = a_row + am * 16;
                int ch = h * 2 + a_kh;
                uint32_t a1[4], a2[4];
                ldsm4(a1, sA + r * 128 + (((ch) ^ (r & 7)) << 4));
                if (TERMS >= 2)
                    ldsm4(a2, sA + r * 128 + (((ch + 4) ^ (r & 7)) << 4));
                #pragma unroll
                for (int g = 0; g < 4; g++) {
                    mma_f16(acc[am][2 * g],     a1, &bh[g][0]);
                    mma_f16(acc[am][2 * g + 1], a1, &bh[g][2]);
                }
                if (TERMS >= 2) {
                    #pragma unroll
                    for (int g = 0; g < 4; g++) {
                        mma_f16(acc[am][2 * g],     a2, &bh[g][0]);
                        mma_f16(acc[am][2 * g + 1], a2, &bh[g][2]);
                    }
                }
                if (TERMS == 3) {
                    #pragma unroll
                    for (int g = 0; g < 4; g++) {
                        mma_f16(acc[am][2 * g],     a1, &bl[g][0]);
                        mma_f16(acc[am][2 * g + 1], a1, &bl[g][2]);
                    }
                }
            }
        }
        __syncthreads();
        if (t + 2 < KB) {
            g_load_stage<TERMS>(sA, A1, A2, B1, B2, bm, bn, t + 2, K, tid);
        }
        CP_COMMIT();
    }

    if (MODE == 0) {
        #pragma unroll
        for (int am = 0; am < 2; am++) {
            int r0 = bm + wm + am * 16 + (lane >> 2);
            #pragma unroll
            for (int an = 0; an < 8; an++) {
                int col = bn + wn + an * 8 + (lane & 3) * 2;
                *(float2*)&C[(size_t)r0 * Nt + col]       = make_float2(acc[am][an][0], acc[am][an][1]);
                *(float2*)&C[(size_t)(r0 + 8) * Nt + col] = make_float2(acc[am][an][2], acc[am][an][3]);
            }
        }
    } else if (MODE == 1) {
        #pragma unroll
        for (int am = 0; am < 2; am++) {
            int r0 = bm + wm + am * 16 + (lane >> 2);
            #pragma unroll
            for (int rh = 0; rh < 2; rh++) {
                int row = r0 + rh * 8;
                int s   = row & (SEQ - 1);
                #pragma unroll
                for (int an = 0; an < 4; an++) {
                    int col = bn + wn + an * 8 + (lane & 3) * 2;
                    int d0  = col & 31;
                    float2 cs0 = *(const float2*)&g_cs[2 * (s * 32 + d0)];
                    float2 cs1 = *(const float2*)&g_cs[2 * (s * 32 + d0 + 1)];
                    float v0a = acc[am][an][rh * 2],     v0b = acc[am][an][rh * 2 + 1];
                    float v1a = acc[am][an + 4][rh * 2], v1b = acc[am][an + 4][rh * 2 + 1];
                    float loa = (v0a * cs0.x - v1a * cs0.y) * rscale;
                    float lob = (v0b * cs1.x - v1b * cs1.y) * rscale;
                    float hia = (v1a * cs0.x + v0a * cs0.y) * rscale;
                    float hib = (v1b * cs1.x + v0b * cs1.y) * rscale;
                    uint32_t hp, lp;
                    split2h(loa, lob, hp, lp);
                    *(uint32_t*)&C1[(size_t)row * Nt + col] = hp;
                    *(uint32_t*)&C2[(size_t)row * Nt + col] = lp;
                    split2h(hia, hib, hp, lp);
                    *(uint32_t*)&C1[(size_t)row * Nt + col + 32] = hp;
                    *(uint32_t*)&C2[(size_t)row * Nt + col + 32] = lp;
                }
            }
        }
    } else {
        #pragma unroll
        for (int am = 0; am < 2; am++) {
            int r0 = bm + wm + am * 16 + (lane >> 2);
            #pragma unroll
            for (int rh = 0; rh < 2; rh++) {
                int row = r0 + rh * 8;
                int bb  = row >> 11;
                int sl  = row & (SEQ - 1);
                #pragma unroll
                for (int an = 0; an < 8; an++) {
                    int col = bn + wn + an * 8 + (lane & 3) * 2;
                    size_t o0 = ((size_t)(bb * NKV + (col >> 6)) * 64 + (col & 63)) * SEQ + sl;
                    C1[o0]       = __float2half(acc[am][an][rh * 2]);
                    C1[o0 + SEQ] = __float2half(acc[am][an][rh * 2 + 1]);
                }
            }
        }
    }
}

// Merged Q+K+V projections: flat 1536-CTA launch.
// [0,1024): Q 2-term rope; [1024,1280): K 3-term rope; [1280,1536): V 2-term.
__global__ __launch_bounds__(128, 4)
void gemm_qkv(const f16* __restrict__ x1, const f16* __restrict__ x2,
              const f16* __restrict__ Wq1,
              const f16* __restrict__ Wk1, const f16* __restrict__ Wk2,
              const f16* __restrict__ Wv1,
              f16* __restrict__ Q1, f16* __restrict__ Q2,
              f16* __restrict__ K1, f16* __restrict__ K2,
              f16* __restrict__ Vt, float qsc) {
    int id = blockIdx.x;
    if (id < 1024) {
        gemm_core<2, 1>(x1, x2, Wq1, nullptr, nullptr, Q1, Q2, qsc,
                        NH * HD, MODEL, (id >> 4) * 64, (id & 15) * 128);
    } else if (id < 1280) {
        id -= 1024;
        gemm_core<3, 1>(x1, x2, Wk1, Wk2, nullptr, K1, K2, 1.0f,
                        KVW, MODEL, (id >> 2) * 64, (id & 3) * 128);
    } else {
        id -= 1280;
        gemm_core<2, 2>(x1, x2, Wv1, nullptr, nullptr, Vt, nullptr, 0.f,
                        KVW, MODEL, (id >> 2) * 64, (id & 3) * 128);
    }
}

// 1-term output projection
__global__ __launch_bounds__(128, 4)
void gemm_out(const f16* __restrict__ Y1, const f16* __restrict__ Wot,
              float* __restrict__ C) {
    gemm_core<1, 0>(Y1, nullptr, Wot, nullptr, C, nullptr, nullptr, 0.f,
                    MODEL, NH * HD, blockIdx.y * 64, blockIdx.x * 128);
}

// ---------------------------------------------------------------------------
// Flash attention: S = fp16 3-term, PV = fp16 2-term, Y out = fp16 hi only.
// ---------------------------------------------------------------------------
#define QSTR 144
#define FA_STG_SZ 27648
#define FA_SQH 55296
#define FA_SQL 73728
#define FA_SMEM 92160

__device__ __forceinline__
void fa_load_kv(uint32_t sb, const f16* __restrict__ K1p, const f16* __restrict__ K2p,
                const f16* __restrict__ Vhp, size_t krow0, int s0, int tid) {
    #pragma unroll
    for (int i = 0; i < 2; i++) {
        int idx = tid + i * 256;
        int r = idx >> 3, c = idx & 7;
        uint32_t so = r * QSTR + c * 16;
        cp16(sb + so,         K1p + (krow0 + r) * KVW + c * 8);
        cp16(sb + 9216 + so,  K2p + (krow0 + r) * KVW + c * 8);
        cp16(sb + 18432 + so, Vhp + (size_t)r * SEQ + s0 + c * 8);
    }
}

__global__ __launch_bounds__(256, 2)
void flashattn_mma(const f16* __restrict__ Q1, const f16* __restrict__ Q2,
                   const f16* __restrict__ K1, const f16* __restrict__ K2,
                   const f16* __restrict__ Vt, f16* __restrict__ Y1) {
    extern __shared__ char sm[];
    const uint32_t base = smem_u32(sm);
    const int tid  = threadIdx.x;
    const int lane = tid & 31;
    const int warp = tid >> 5;
    const int qt   = gridDim.x - 1 - blockIdx.x;
    const int h    = blockIdx.y;
    const int b    = blockIdx.z;
    const int kvh  = h >> 2;
    const int wm   = warp * 16;

    const f16* K1p = K1 + kvh * 64;
    const f16* K2p = K2 + kvh * 64;
    const f16* Vhp = Vt + (size_t)((b * NKV + kvh) * 64) * SEQ;
    const int njt = 2 * qt + 2;

    {
        size_t qrow0 = (size_t)(b * SEQ + qt * 128);
        int hoff = h * HD;
        #pragma unroll
        for (int i = 0; i < 4; i++) {
            int idx = tid + i * 256;
            int r = idx >> 3, c = idx & 7;
            cp16(base + FA_SQH + r * QSTR + c * 16, Q1 + (qrow0 + r) * (NH * HD) + hoff + c * 8);
            cp16(base + FA_SQL + r * QSTR + c * 16, Q2 + (qrow0 + r) * (NH * HD) + hoff + c * 8);
        }
    }
    CP_COMMIT();
    fa_load_kv(base, K1p, K2p, Vhp, (size_t)b * SEQ, 0, tid);
    CP_COMMIT();
    CP_WAIT1();
    __syncthreads();

    const int a_row = wm + (lane & 15);
    const int a_kh  = (lane >> 4) & 1;
    uint32_t qf1[4][4], qf2[4][4];
    {
        uint32_t qa = base + a_row * QSTR + a_kh * 16;
        #pragma unroll
        for (int kc = 0; kc < 4; kc++) {
            ldsm4(qf1[kc], qa + FA_SQH + kc * 32);
            ldsm4(qf2[kc], qa + FA_SQL + kc * 32);
        }
    }

    const int b_n  = (lane & 7) + ((lane >> 4) << 3);
    const int b_kh = (lane >> 3) & 1;
    const uint32_t KVoff = (uint32_t)(b_n * QSTR + b_kh * 16);

    float m0 = -INFINITY, m1 = -INFINITY, l0 = 0.f, l1 = 0.f;
    float oa[8][4];
    #pragma unroll
    for (int f = 0; f < 8; f++)
        #pragma unroll
        for (int j = 0; j < 4; j++) oa[f][j] = 0.f;

    for (int jt = 0; jt < njt; jt++) {
        __syncthreads();
        if (jt + 1 < njt) {
            fa_load_kv(base + ((jt + 1) & 1) * FA_STG_SZ,
                       K1p, K2p, Vhp,
                       (size_t)b * SEQ + (jt + 1) * 64, (jt + 1) * 64, tid);
        }
        CP_COMMIT();
        CP_WAIT1();
        __syncthreads();

        const uint32_t stgKV = base + (jt & 1) * FA_STG_SZ + KVoff;

        float sa[8][4];
        #pragma unroll
        for (int f = 0; f < 8; f++)
            #pragma unroll
            for (int j = 0; j < 4; j++) sa[f][j] = 0.f;

        #pragma unroll
        for (int kc = 0; kc < 4; kc++) {
            #pragma unroll
            for (int g = 0; g < 4; g++) {
                uint32_t k14[4], k24[4];
                ldsm4(k14, stgKV + g * (16 * QSTR) + kc * 32);
                ldsm4(k24, stgKV + 9216 + g * (16 * QSTR) + kc * 32);
                mma_f16(sa[2 * g],     qf1[kc], &k14[0]);
                mma_f16(sa[2 * g + 1], qf1[kc], &k14[2]);
                mma_f16(sa[2 * g],     qf2[kc], &k14[0]);
                mma_f16(sa[2 * g + 1], qf2[kc], &k14[2]);
                mma_f16(sa[2 * g],     qf1[kc], &k24[0]);
                mma_f16(sa[2 * g + 1], qf1[kc], &k24[2]);
            }
        }

        if (jt * 64 + 63 > qt * 128) {
            int r0g = qt * 128 + wm + (lane >> 2);
            int r1g = r0g + 8;
            #pragma unroll
            for (int f = 0; f < 8; f++) {
                int c0 = jt * 64 + f * 8 + (lane & 3) * 2;
                if (c0 > r0g)     sa[f][0] = -INFINITY;
                if (c0 + 1 > r0g) sa[f][1] = -INFINITY;
                if (c0 > r1g)     sa[f][2] = -INFINITY;
                if (c0 + 1 > r1g) sa[f][3] = -INFINITY;
            }
        }

        float rm0 = -INFINITY, rm1 = -INFINITY;
        #pragma unroll
        for (int f = 0; f < 8; f++) {
            rm0 = fmaxf(rm0, fmaxf(sa[f][0], sa[f][1]));
            rm1 = fmaxf(rm1, fmaxf(sa[f][2], sa[f][3]));
        }
        rm0 = fmaxf(rm0, __shfl_xor_sync(0xffffffffu, rm0, 1));
        rm0 = fmaxf(rm0, __shfl_xor_sync(0xffffffffu, rm0, 2));
        rm1 = fmaxf(rm1, __shfl_xor_sync(0xffffffffu, rm1, 1));
        rm1 = fmaxf(rm1, __shfl_xor_sync(0xffffffffu, rm1, 2));

        float mn0 = fmaxf(m0, rm0), mn1 = fmaxf(m1, rm1);
        float f0 = exp2f(m0 - mn0), f1 = exp2f(m1 - mn1);
        float rs0 = 0.f, rs1 = 0.f;
        #pragma unroll
        for (int f = 0; f < 8; f++) {
            sa[f][0] = exp2f(sa[f][0] - mn0);
            sa[f][1] = exp2f(sa[f][1] - mn0);
            sa[f][2] = exp2f(sa[f][2] - mn1);
            sa[f][3] = exp2f(sa[f][3] - mn1);
            rs0 += sa[f][0] + sa[f][1];
            rs1 += sa[f][2] + sa[f][3];
        }
        rs0 += __shfl_xor_sync(0xffffffffu, rs0, 1);
        rs0 += __shfl_xor_sync(0xffffffffu, rs0, 2);
        rs1 += __shfl_xor_sync(0xffffffffu, rs1, 1);
        rs1 += __shfl_xor_sync(0xffffffffu, rs1, 2);

        l0 = l0 * f0 + rs0;  m0 = mn0;
        l1 = l1 * f1 + rs1;  m1 = mn1;
        #pragma unroll
        for (int f = 0; f < 8; f++) {
            oa[f][0] *= f0; oa[f][1] *= f0;
            oa[f][2] *= f1; oa[f][3] *= f1;
        }

        #pragma unroll
        for (int kc = 0; kc < 4; kc++) {
            uint32_t p1[4], p2[4];
            split2h(sa[2 * kc][0],     sa[2 * kc][1],     p1[0], p2[0]);
            split2h(sa[2 * kc][2],     sa[2 * kc][3],     p1[1], p2[1]);
            split2h(sa[2 * kc + 1][0], sa[2 * kc + 1][1], p1[2], p2[2]);
            split2h(sa[2 * kc + 1][2], sa[2 * kc + 1][3], p1[3], p2[3]);
            #pragma unroll
            for (int g = 0; g < 4; g++) {
                uint32_t vh4[4];
                ldsm4(vh4, stgKV + 18432 + g * (16 * QSTR) + kc * 32);
                mma_f16(oa[2 * g],     p1, &vh4[0]);
                mma_f16(oa[2 * g + 1], p1, &vh4[2]);
                mma_f16(oa[2 * g],     p2, &vh4[0]);
                mma_f16(oa[2 * g + 1], p2, &vh4[2]);
            }
        }
    }

    // epilogue: normalize, fp16 hi only
    float inv0 = 1.f / l0, inv1 = 1.f / l1;
    size_t row0 = (size_t)(b * SEQ + qt * 128 + wm + (lane >> 2));
    #pragma unroll
    for (int f = 0; f < 8; f++) {
        int col = h * HD + f * 8 + (lane & 3) * 2;
        *(uint32_t*)&Y1[row0 * (NH * HD) + col] =
            pkhf2(oa[f][0] * inv0, oa[f][1] * inv0);
        *(uint32_t*)&Y1[(row0 + 8) * (NH * HD) + col] =
            pkhf2(oa[f][2] * inv1, oa[f][3] * inv1);
    }
}

// ---------------------------------------------------------------------------
extern "C" void kernel_launch(void* const* d_in, const int* in_sizes, int n_in,
                              void* d_out, int out_size) {
    const float* x  = (const float*)d_in[0];
    const float* Wq = (const float*)d_in[1];
    const float* Wk = (const float*)d_in[2];
    const float* Wv = (const float*)d_in[3];
    const float* Wo = (const float*)d_in[4];
    float* out = (float*)d_out;

    f16 *x1, *x2, *Q1, *Q2, *K1, *K2, *Vt, *Y1;
    f16 *Wq1, *Wk1, *Wk2, *Wv1, *Wot;
    cudaGetSymbolAddress((void**)&x1, g_x1);   cudaGetSymbolAddress((void**)&x2, g_x2);
    cudaGetSymbolAddress((void**)&Q1, g_Q1);   cudaGetSymbolAddress((void**)&Q2, g_Q2);
    cudaGetSymbolAddress((void**)&K1, g_K1);   cudaGetSymbolAddress((void**)&K2, g_K2);
    cudaGetSymbolAddress((void**)&Vt, g_Vt);
    cudaGetSymbolAddress((void**)&Y1, g_Y1);
    cudaGetSymbolAddress((void**)&Wq1, g_Wqt1);
    cudaGetSymbolAddress((void**)&Wk1, g_Wkt1); cudaGetSymbolAddress((void**)&Wk2, g_Wkt2);
    cudaGetSymbolAddress((void**)&Wv1, g_Wvt1);
    cudaGetSymbolAddress((void**)&Wot, g_Wot);

    dim3 blk(256);
    dim3 gblk(128);
    const float QSC = 0.125f * 1.4426950408889634f;

    rope_table<<<(SEQ * 32 + 255) / 256, blk>>>();
    int totx = ROWS * MODEL;
    split_rows_h<<<(totx + 255) / 256, blk>>>(x, x1, x2, totx);
    ts_all<<<dim3(64, 64, 4), blk>>>(Wq, Wk, Wv, Wo);

    cudaFuncSetAttribute(gemm_qkv, cudaFuncAttributeMaxDynamicSharedMemorySize, GEMM_SMEM);
    cudaFuncSetAttribute(gemm_out, cudaFuncAttributeMaxDynamicSharedMemorySize, GEMM_SMEM);

    // merged Q + K + V projections
    gemm_qkv<<<1536, gblk, GEMM_SMEM>>>(x1, x2, Wq1, Wk1, Wk2, Wv1,
                                        Q1, Q2, K1, K2, Vt, QSC);

    cudaFuncSetAttribute(flashattn_mma, cudaFuncAttributeMaxDynamicSharedMemorySize, FA_SMEM);
    flashattn_mma<<<dim3(SEQ / 128, NH, BATCH), blk, FA_SMEM>>>(
        Q1, Q2, K1, K2, Vt, Y1);

    // 1-term output projection
    gemm_out<<<dim3(MODEL / 128, ROWS / 64), gblk, GEMM_SMEM>>>(Y1, Wot, out);
}